// round 11
// baseline (speedup 1.0000x reference)
#include <cuda_runtime.h>
#include <cuda_bf16.h>
#include <math.h>
#include <stdint.h>

// ---------------- problem constants ----------------
#define MB    8
#define NCC   512
#define NTOK  1024
#define DMOD  256
#define NH    8
#define NLAY  6
#define FFD   1024
#define DHD   32
#define TOK   (MB * NTOK)   // 8192

// ---------------- device scratch ----------------
__device__ float g_z[TOK * DMOD];
// split activations (bf16 hi/lo packed as uint32 pairs)
__device__ uint32_t g_h_h[TOK * DMOD / 2],  g_h_l[TOK * DMOD / 2];
__device__ uint32_t g_qkv_h[TOK * 3 * DMOD / 2], g_qkv_l[TOK * 3 * DMOD / 2];
__device__ uint32_t g_att_h[TOK * DMOD / 2], g_att_l[TOK * DMOD / 2];
__device__ uint32_t g_ff_h[TOK * FFD / 2],   g_ff_l[TOK * FFD / 2];
// split weights [K][N]
__device__ uint32_t g_wqkv_h[NLAY * DMOD * 3 * DMOD / 2], g_wqkv_l[NLAY * DMOD * 3 * DMOD / 2];
__device__ uint32_t g_wo_h[NLAY * DMOD * DMOD / 2],       g_wo_l[NLAY * DMOD * DMOD / 2];
__device__ uint32_t g_wff1_h[NLAY * DMOD * FFD / 2],      g_wff1_l[NLAY * DMOD * FFD / 2];
__device__ uint32_t g_wff2_h[NLAY * FFD * DMOD / 2],      g_wff2_l[NLAY * FFD * DMOD / 2];
__device__ uint32_t g_ew2_h[DMOD * DMOD / 2],             g_ew2_l[DMOD * DMOD / 2];

// ---------------- helpers ----------------
__device__ __forceinline__ void split2(float x0, float x1, uint32_t& h, uint32_t& l) {
    uint32_t hh;
    asm("cvt.rn.bf16x2.f32 %0, %1, %2;" : "=r"(hh) : "f"(x1), "f"(x0));
    float h0f = __uint_as_float(hh << 16);
    float h1f = __uint_as_float(hh & 0xffff0000u);
    h = hh;
    float l0 = x0 - h0f, l1 = x1 - h1f;
    asm("cvt.rn.bf16x2.f32 %0, %1, %2;" : "=r"(l) : "f"(l1), "f"(l0));
}
__device__ __forceinline__ float bflo(uint32_t v) { return __uint_as_float(v << 16); }
__device__ __forceinline__ float bfhi(uint32_t v) { return __uint_as_float(v & 0xffff0000u); }

__device__ __forceinline__ void cp_async16(void* dst, const void* src) {
    uint32_t d = (uint32_t)__cvta_generic_to_shared(dst);
    asm volatile("cp.async.cg.shared.global [%0], [%1], 16;\n" :: "r"(d), "l"(src));
}
__device__ __forceinline__ void cp_commit() { asm volatile("cp.async.commit_group;\n"); }
template <int N>
__device__ __forceinline__ void cp_wait() { asm volatile("cp.async.wait_group %0;\n" :: "n"(N)); }

__device__ __forceinline__ uint32_t smem_u32(const void* p) {
    return (uint32_t)__cvta_generic_to_shared(p);
}

#define LDM4(R0, R1, R2, R3, ADDR)                                          \
    asm volatile("ldmatrix.sync.aligned.m8n8.x4.shared.b16 {%0,%1,%2,%3}, [%4];" \
                 : "=r"(R0), "=r"(R1), "=r"(R2), "=r"(R3) : "r"(ADDR))

#define LDM4T(R0, R1, R2, R3, ADDR)                                         \
    asm volatile("ldmatrix.sync.aligned.m8n8.x4.trans.shared.b16 {%0,%1,%2,%3}, [%4];" \
                 : "=r"(R0), "=r"(R1), "=r"(R2), "=r"(R3) : "r"(ADDR))

#define MMA_BF16(ACC, A0, A1, A2, A3, B0, B1)                               \
    asm volatile(                                                           \
        "mma.sync.aligned.m16n8k16.row.col.f32.bf16.bf16.f32 "             \
        "{%0,%1,%2,%3}, {%4,%5,%6,%7}, {%8,%9}, {%0,%1,%2,%3};"            \
        : "+f"((ACC)[0]), "+f"((ACC)[1]), "+f"((ACC)[2]), "+f"((ACC)[3])   \
        : "r"(A0), "r"(A1), "r"(A2), "r"(A3), "r"(B0), "r"(B1))

// ---------------- merged weight split: fp32 -> bf16 hi/lo, all weights ----------------
#define P_EW  (DMOD * DMOD / 2)                    // 32768
#define P_QKV (NLAY * DMOD * 3 * DMOD / 2)         // 589824
#define P_WO  (NLAY * DMOD * DMOD / 2)             // 196608
#define P_FF1 (NLAY * DMOD * FFD / 2)              // 786432
#define P_FF2 (NLAY * FFD * DMOD / 2)              // 786432
#define P_TOT (P_EW + P_QKV + P_WO + P_FF1 + P_FF2)

__global__ __launch_bounds__(256) void split_all(
    const float* __restrict__ enc_W2, const float* __restrict__ Wqkv,
    const float* __restrict__ Wo, const float* __restrict__ Wff1,
    const float* __restrict__ Wff2)
{
    int i = blockIdx.x * 256 + threadIdx.x;
    if (i >= P_TOT) return;
    const float* src;
    uint32_t *hi, *lo;
    int j;
    if (i < P_EW) {
        j = i; src = enc_W2; hi = g_ew2_h; lo = g_ew2_l;
    } else if (i < P_EW + P_QKV) {
        j = i - P_EW; src = Wqkv; hi = g_wqkv_h; lo = g_wqkv_l;
    } else if (i < P_EW + P_QKV + P_WO) {
        j = i - (P_EW + P_QKV); src = Wo; hi = g_wo_h; lo = g_wo_l;
    } else if (i < P_EW + P_QKV + P_WO + P_FF1) {
        j = i - (P_EW + P_QKV + P_WO); src = Wff1; hi = g_wff1_h; lo = g_wff1_l;
    } else {
        j = i - (P_EW + P_QKV + P_WO + P_FF1); src = Wff2; hi = g_wff2_h; lo = g_wff2_l;
    }
    uint32_t h, l;
    split2(src[2 * j], src[2 * j + 1], h, l);
    hi[j] = h;
    lo[j] = l;
}

// ---------------- pure-bf16 3-pass tensor-core GEMM (256 thr, 8 warps) ----------------
// BMV=64 (warp tile 32x32): ~80 regs -> 2-3 CTAs/SM. Used for ALL gemms now;
// BMV=128 kept for reference/fallback.
#define BN 128
#define BK 32
#define AST 40    // bf16 stride (80 B rows)
#define BST 136   // bf16 stride (272 B rows)
#define ASTB 80
#define BSTB 272
#define GEMM_SMEM(BMV) ((2*(BMV)*AST + 2*BK*BST) * 2 * 2)

// OUTMODE: 0 fp32, 1 fp32+resid, 2 relu+split, 3 split
template <int OUTMODE, int BMV>
__global__ __launch_bounds__(256) void gemm_bf3(
    const __nv_bfloat16* __restrict__ Ah, const __nv_bfloat16* __restrict__ Al,
    const __nv_bfloat16* __restrict__ Bh, const __nv_bfloat16* __restrict__ Bl,
    const float* __restrict__ bias, const float* __restrict__ Rsd,
    float* __restrict__ C, uint32_t* __restrict__ Chi, uint32_t* __restrict__ Clo,
    int K, int N)
{
    constexpr int MI = BMV / 32;          // m16 fragments per warp
    extern __shared__ char smem_raw[];
    __nv_bfloat16* sAh = (__nv_bfloat16*)smem_raw;
    __nv_bfloat16* sAl = sAh + 2 * BMV * AST;
    __nv_bfloat16* sBh = sAl + 2 * BMV * AST;
    __nv_bfloat16* sBl = sBh + 2 * BK * BST;

    const int tid = threadIdx.x;
    const int warp = tid >> 5, lane = tid & 31;
    const int g = lane >> 2, tg = lane & 3;
    const int wy = warp >> 2, wx = warp & 3;   // 2x4 warps
    const int row0 = blockIdx.y * BMV, col0 = blockIdx.x * BN;

    float acc[MI][4][4];
    #pragma unroll
    for (int a = 0; a < MI; a++)
        #pragma unroll
        for (int b = 0; b < 4; b++)
            #pragma unroll
            for (int c = 0; c < 4; c++) acc[a][b][c] = 0.0f;

    auto issue = [&](int t, int b) {
        #pragma unroll
        for (int s = tid; s < BMV * 4; s += 256) {
            int arow = s >> 2, aseg = s & 3;
            cp_async16(sAh + b * BMV * AST + arow * AST + aseg * 8,
                       Ah + (size_t)(row0 + arow) * K + t * BK + aseg * 8);
            cp_async16(sAl + b * BMV * AST + arow * AST + aseg * 8,
                       Al + (size_t)(row0 + arow) * K + t * BK + aseg * 8);
        }
        #pragma unroll
        for (int s = tid; s < 512; s += 256) {
            int brow = s >> 4, bseg = s & 15;
            cp_async16(sBh + b * BK * BST + brow * BST + bseg * 8,
                       Bh + (size_t)(t * BK + brow) * N + col0 + bseg * 8);
            cp_async16(sBl + b * BK * BST + brow * BST + bseg * 8,
                       Bl + (size_t)(t * BK + brow) * N + col0 + bseg * 8);
        }
        cp_commit();
    };

    const int a_lane = (wy * (BMV / 2) + (lane & 15)) * ASTB + (lane >> 4) * 16;
    const int b_lane = (lane & 15) * BSTB + (lane >> 4) * 16 + wx * 64;

    auto compute = [&](int b) {
        uint32_t aHb = smem_u32(sAh + b * BMV * AST) + a_lane;
        uint32_t aLb = smem_u32(sAl + b * BMV * AST) + a_lane;
        uint32_t bHb = smem_u32(sBh + b * BK * BST) + b_lane;
        uint32_t bLb = smem_u32(sBl + b * BK * BST) + b_lane;

        #pragma unroll
        for (int ks = 0; ks < 2; ks++) {
            uint32_t ah[MI][4], al[MI][4], bh[2][4], bl[2][4];
            #pragma unroll
            for (int mi = 0; mi < MI; mi++) {
                LDM4(ah[mi][0], ah[mi][1], ah[mi][2], ah[mi][3],
                     aHb + mi * 16 * ASTB + ks * 32);
                LDM4(al[mi][0], al[mi][1], al[mi][2], al[mi][3],
                     aLb + mi * 16 * ASTB + ks * 32);
            }
            #pragma unroll
            for (int nc = 0; nc < 2; nc++) {
                LDM4T(bh[nc][0], bh[nc][1], bh[nc][2], bh[nc][3],
                      bHb + ks * 16 * BSTB + nc * 32);
                LDM4T(bl[nc][0], bl[nc][1], bl[nc][2], bl[nc][3],
                      bLb + ks * 16 * BSTB + nc * 32);
            }
            #pragma unroll
            for (int mi = 0; mi < MI; mi++)
                #pragma unroll
                for (int nf = 0; nf < 4; nf++) {
                    const int p = nf >> 1, q = (nf & 1) * 2;
                    MMA_BF16(acc[mi][nf], al[mi][0], al[mi][1], al[mi][2], al[mi][3],
                             bh[p][q], bh[p][q + 1]);
                    MMA_BF16(acc[mi][nf], ah[mi][0], ah[mi][1], ah[mi][2], ah[mi][3],
                             bl[p][q], bl[p][q + 1]);
                    MMA_BF16(acc[mi][nf], ah[mi][0], ah[mi][1], ah[mi][2], ah[mi][3],
                             bh[p][q], bh[p][q + 1]);
                }
        }
    };

    const int T = K / BK;
    issue(0, 0);
    for (int t = 0; t < T; t++) {
        const int buf = t & 1;
        if (t + 1 < T) {
            issue(t + 1, buf ^ 1);
            cp_wait<1>();
        } else {
            cp_wait<0>();
        }
        __syncthreads();
        compute(buf);
        __syncthreads();
    }

    #pragma unroll
    for (int mi = 0; mi < MI; mi++) {
        #pragma unroll
        for (int nf = 0; nf < 4; nf++) {
            const int r = row0 + wy * (BMV / 2) + mi * 16 + g;
            const int c = col0 + wx * 32 + nf * 8 + tg * 2;
            const float b0 = bias[c], b1 = bias[c + 1];
            float v0 = acc[mi][nf][0] + b0;
            float v1 = acc[mi][nf][1] + b1;
            float v2 = acc[mi][nf][2] + b0;
            float v3 = acc[mi][nf][3] + b1;
            if (OUTMODE >= 2) {
                if (OUTMODE == 2) {
                    v0 = fmaxf(v0, 0.0f); v1 = fmaxf(v1, 0.0f);
                    v2 = fmaxf(v2, 0.0f); v3 = fmaxf(v3, 0.0f);
                }
                uint32_t h, l;
                split2(v0, v1, h, l);
                Chi[((size_t)r * N + c) >> 1] = h;
                Clo[((size_t)r * N + c) >> 1] = l;
                split2(v2, v3, h, l);
                Chi[((size_t)(r + 8) * N + c) >> 1] = h;
                Clo[((size_t)(r + 8) * N + c) >> 1] = l;
            } else {
                if (OUTMODE == 1) {
                    v0 += Rsd[(size_t)r * N + c];
                    v1 += Rsd[(size_t)r * N + c + 1];
                    v2 += Rsd[(size_t)(r + 8) * N + c];
                    v3 += Rsd[(size_t)(r + 8) * N + c + 1];
                }
                *(float2*)&C[(size_t)r * N + c]       = make_float2(v0, v1);
                *(float2*)&C[(size_t)(r + 8) * N + c] = make_float2(v2, v3);
            }
        }
    }
}

// ---------------- tensor-core flash attention (R7, unchanged) ----------------
#define QST 40
#define QSTB 80
#define ATTN_SMEM ((2*64*QST + 8*64*QST) * 2)   // 51200 bytes

__global__ __launch_bounds__(128) void attn_mma(
    const uint32_t* __restrict__ qh, const uint32_t* __restrict__ ql,
    uint32_t* __restrict__ oh, uint32_t* __restrict__ ol)
{
    extern __shared__ char sm[];
    __nv_bfloat16* sQh = (__nv_bfloat16*)sm;
    __nv_bfloat16* sQl = sQh + 64 * QST;
    __nv_bfloat16* sKh = sQl + 64 * QST;
    __nv_bfloat16* sKl = sKh + 2 * 64 * QST;
    __nv_bfloat16* sVh = sKl + 2 * 64 * QST;
    __nv_bfloat16* sVl = sVh + 2 * 64 * QST;

    const int mh = blockIdx.x, qb = blockIdx.y;
    const int m = mh >> 3, h = mh & 7;
    const int q0 = qb * 64;
    const int tid = threadIdx.x, warp = tid >> 5, lane = tid & 31;
    const int g = lane >> 2, tg = lane & 3;
    const int tb = m * NTOK;
    const float scale = 0.17677669529663687f;

    const int i0 = tid * 2;
    const int lrow0 = i0 >> 2, lseg0 = i0 & 3;
    const int lrow1 = (i0 + 1) >> 2, lseg1 = (i0 + 1) & 3;

    {
        size_t s0 = (size_t)(tb + q0 + lrow0) * 384 + h * 16 + lseg0 * 4;
        size_t s1 = (size_t)(tb + q0 + lrow1) * 384 + h * 16 + lseg1 * 4;
        cp_async16(sQh + lrow0 * QST + lseg0 * 8, qh + s0);
        cp_async16(sQh + lrow1 * QST + lseg1 * 8, qh + s1);
        cp_async16(sQl + lrow0 * QST + lseg0 * 8, ql + s0);
        cp_async16(sQl + lrow1 * QST + lseg1 * 8, ql + s1);
        cp_commit();
    }
    auto issueKV = [&](int c, int b) {
        int k0 = c * 64;
        size_t s0 = (size_t)(tb + k0 + lrow0) * 384 + 128 + h * 16 + lseg0 * 4;
        size_t s1 = (size_t)(tb + k0 + lrow1) * 384 + 128 + h * 16 + lseg1 * 4;
        __nv_bfloat16* kh = sKh + b * 64 * QST;
        __nv_bfloat16* kl = sKl + b * 64 * QST;
        __nv_bfloat16* vh = sVh + b * 64 * QST;
        __nv_bfloat16* vl = sVl + b * 64 * QST;
        cp_async16(kh + lrow0 * QST + lseg0 * 8, qh + s0);
        cp_async16(kh + lrow1 * QST + lseg1 * 8, qh + s1);
        cp_async16(kl + lrow0 * QST + lseg0 * 8, ql + s0);
        cp_async16(kl + lrow1 * QST + lseg1 * 8, ql + s1);
        cp_async16(vh + lrow0 * QST + lseg0 * 8, qh + s0 + 128);
        cp_async16(vh + lrow1 * QST + lseg1 * 8, qh + s1 + 128);
        cp_async16(vl + lrow0 * QST + lseg0 * 8, ql + s0 + 128);
        cp_async16(vl + lrow1 * QST + lseg1 * 8, ql + s1 + 128);
        cp_commit();
    };

    issueKV(0, 0);
    cp_wait<1>();
    __syncthreads();

    uint32_t qfh[2][4], qfl[2][4];
    {
        uint32_t bh_ = smem_u32(sQh) + (warp * 16 + (lane & 15)) * QSTB + (lane >> 4) * 16;
        uint32_t bl_ = smem_u32(sQl) + (warp * 16 + (lane & 15)) * QSTB + (lane >> 4) * 16;
        LDM4(qfh[0][0], qfh[0][1], qfh[0][2], qfh[0][3], bh_);
        LDM4(qfh[1][0], qfh[1][1], qfh[1][2], qfh[1][3], bh_ + 32);
        LDM4(qfl[0][0], qfl[0][1], qfl[0][2], qfl[0][3], bl_);
        LDM4(qfl[1][0], qfl[1][1], qfl[1][2], qfl[1][3], bl_ + 32);
    }

    float mx0 = -1e30f, mx1 = -1e30f, sum0 = 0.f, sum1 = 0.f;
    float oacc[4][4];
    #pragma unroll
    for (int a = 0; a < 4; a++)
        #pragma unroll
        for (int b = 0; b < 4; b++) oacc[a][b] = 0.f;

    const uint32_t kbyte = ((lane & 7) + ((lane >> 4) & 1) * 8) * QSTB +
                           ((lane >> 3) & 1) * 16;
    const uint32_t vbyte = (lane & 15) * QSTB + (lane >> 4) * 16;

    for (int c = 0; c < 8; c++) {
        const int b = c & 1;
        if (c + 1 < 8) { issueKV(c + 1, b ^ 1); cp_wait<1>(); }
        else           { cp_wait<0>(); }
        __syncthreads();

        uint32_t khb = smem_u32(sKh + b * 64 * QST) + kbyte;
        uint32_t klb = smem_u32(sKl + b * 64 * QST) + kbyte;

        float sacc[8][4];
        #pragma unroll
        for (int a = 0; a < 8; a++)
            #pragma unroll
            for (int j = 0; j < 4; j++) sacc[a][j] = 0.f;

        #pragma unroll
        for (int nk = 0; nk < 4; nk++) {
            uint32_t kh0[4], kh1[4], kl0[4], kl1[4];
            LDM4(kh0[0], kh0[1], kh0[2], kh0[3], khb + nk * 16 * QSTB);
            LDM4(kh1[0], kh1[1], kh1[2], kh1[3], khb + nk * 16 * QSTB + 32);
            LDM4(kl0[0], kl0[1], kl0[2], kl0[3], klb + nk * 16 * QSTB);
            LDM4(kl1[0], kl1[1], kl1[2], kl1[3], klb + nk * 16 * QSTB + 32);
            MMA_BF16(sacc[nk*2], qfl[0][0], qfl[0][1], qfl[0][2], qfl[0][3], kh0[0], kh0[1]);
            MMA_BF16(sacc[nk*2], qfl[1][0], qfl[1][1], qfl[1][2], qfl[1][3], kh1[0], kh1[1]);
            MMA_BF16(sacc[nk*2], qfh[0][0], qfh[0][1], qfh[0][2], qfh[0][3], kl0[0], kl0[1]);
            MMA_BF16(sacc[nk*2], qfh[1][0], qfh[1][1], qfh[1][2], qfh[1][3], kl1[0], kl1[1]);
            MMA_BF16(sacc[nk*2], qfh[0][0], qfh[0][1], qfh[0][2], qfh[0][3], kh0[0], kh0[1]);
            MMA_BF16(sacc[nk*2], qfh[1][0], qfh[1][1], qfh[1][2], qfh[1][3], kh1[0], kh1[1]);
            MMA_BF16(sacc[nk*2+1], qfl[0][0], qfl[0][1], qfl[0][2], qfl[0][3], kh0[2], kh0[3]);
            MMA_BF16(sacc[nk*2+1], qfl[1][0], qfl[1][1], qfl[1][2], qfl[1][3], kh1[2], kh1[3]);
            MMA_BF16(sacc[nk*2+1], qfh[0][0], qfh[0][1], qfh[0][2], qfh[0][3], kl0[2], kl0[3]);
            MMA_BF16(sacc[nk*2+1], qfh[1][0], qfh[1][1], qfh[1][2], qfh[1][3], kl1[2], kl1[3]);
            MMA_BF16(sacc[nk*2+1], qfh[0][0], qfh[0][1], qfh[0][2], qfh[0][3], kh0[2], kh0[3]);
            MMA_BF16(sacc[nk*2+1], qfh[1][0], qfh[1][1], qfh[1][2], qfh[1][3], kh1[2], kh1[3]);
        }

        float cm0 = -1e30f, cm1 = -1e30f;
        #pragma unroll
        for (int a = 0; a < 8; a++) {
            #pragma unroll
            for (int j = 0; j < 4; j++) sacc[a][j] *= scale;
            cm0 = fmaxf(cm0, fmaxf(sacc[a][0], sacc[a][1]));
            cm1 = fmaxf(cm1, fmaxf(sacc[a][2], sacc[a][3]));
        }
        cm0 = fmaxf(cm0, __shfl_xor_sync(~0u, cm0, 1));
        cm0 = fmaxf(cm0, __shfl_xor_sync(~0u, cm0, 2));
        cm1 = fmaxf(cm1, __shfl_xor_sync(~0u, cm1, 1));
        cm1 = fmaxf(cm1, __shfl_xor_sync(~0u, cm1, 2));
        float nm0 = fmaxf(mx0, cm0), nm1 = fmaxf(mx1, cm1);
        float c0 = __expf(mx0 - nm0), c1 = __expf(mx1 - nm1);
        sum0 *= c0; sum1 *= c1;
        #pragma unroll
        for (int a = 0; a < 4; a++) {
            oacc[a][0] *= c0; oacc[a][1] *= c0;
            oacc[a][2] *= c1; oacc[a][3] *= c1;
        }
        #pragma unroll
        for (int a = 0; a < 8; a++) {
            sacc[a][0] = __expf(sacc[a][0] - nm0);
            sacc[a][1] = __expf(sacc[a][1] - nm0);
            sacc[a][2] = __expf(sacc[a][2] - nm1);
            sacc[a][3] = __expf(sacc[a][3] - nm1);
            sum0 += sacc[a][0] + sacc[a][1];
            sum1 += sacc[a][2] + sacc[a][3];
        }
        mx0 = nm0; mx1 = nm1;

        uint32_t pah[4][4], pal[4][4];
        #pragma unroll
        for (int kf = 0; kf < 4; kf++) {
            split2(sacc[kf*2][0],   sacc[kf*2][1],   pah[kf][0], pal[kf][0]);
            split2(sacc[kf*2][2],   sacc[kf*2][3],   pah[kf][1], pal[kf][1]);
            split2(sacc[kf*2+1][0], sacc[kf*2+1][1], pah[kf][2], pal[kf][2]);
            split2(sacc[kf*2+1][2], sacc[kf*2+1][3], pah[kf][3], pal[kf][3]);
        }

        uint32_t vhb = smem_u32(sVh + b * 64 * QST) + vbyte;
        uint32_t vlb = smem_u32(sVl + b * 64 * QST) + vbyte;
        #pragma unroll
        for (int nc = 0; nc < 2; nc++) {
            #pragma unroll
            for (int kf = 0; kf < 4; kf++) {
                uint32_t vh_[4], vl_[4];
                LDM4T(vh_[0], vh_[1], vh_[2], vh_[3], vhb + kf * 16 * QSTB + nc * 32);
                LDM4T(vl_[0], vl_[1], vl_[2], vl_[3], vlb + kf * 16 * QSTB + nc * 32);
                MMA_BF16(oacc[nc*2], pal[kf][0], pal[kf][1], pal[kf][2], pal[kf][3], vh_[0], vh_[1]);
                MMA_BF16(oacc[nc*2], pah[kf][0], pah[kf][1], pah[kf][2], pah[kf][3], vl_[0], vl_[1]);
                MMA_BF16(oacc[nc*2], pah[kf][0], pah[kf][1], pah[kf][2], pah[kf][3], vh_[0], vh_[1]);
                MMA_BF16(oacc[nc*2+1], pal[kf][0], pal[kf][1], pal[kf][2], pal[kf][3], vh_[2], vh_[3]);
                MMA_BF16(oacc[nc*2+1], pah[kf][0], pah[kf][1], pah[kf][2], pah[kf][3], vl_[2], vl_[3]);
                MMA_BF16(oacc[nc*2+1], pah[kf][0], pah[kf][1], pah[kf][2], pah[kf][3], vh_[2], vh_[3]);
            }
        }
        __syncthreads();
    }

    if (q0 >= NCC) {
        #pragma unroll
        for (int half = 0; half < 2; half++) {
            int row = q0 + warp * 16 + g + half * 8;
            size_t pb = (size_t)(tb + row) * 384;
            float dot = 0.f;
            #pragma unroll
            for (int w = 0; w < 4; w++) {
                uint32_t qhv = qh[pb + h * 16 + tg * 4 + w];
                uint32_t qlv = ql[pb + h * 16 + tg * 4 + w];
                uint32_t khv = qh[pb + 128 + h * 16 + tg * 4 + w];
                uint32_t klv = ql[pb + 128 + h * 16 + tg * 4 + w];
                float qa = bflo(qhv) + bflo(qlv), qb_ = bfhi(qhv) + bfhi(qlv);
                float ka = bflo(khv) + bflo(klv), kb = bfhi(khv) + bfhi(klv);
                dot += qa * ka + qb_ * kb;
            }
            dot += __shfl_xor_sync(~0u, dot, 1);
            dot += __shfl_xor_sync(~0u, dot, 2);
            float s = dot * scale;
            float mxv = half ? mx1 : mx0;
            float nm = fmaxf(mxv, s);
            float corr = __expf(mxv - nm);
            float p = __expf(s - nm);
            if (half) { sum1 = sum1 * corr + (tg == 0 ? p : 0.f); mx1 = nm; }
            else      { sum0 = sum0 * corr + (tg == 0 ? p : 0.f); mx0 = nm; }
            #pragma unroll
            for (int nf = 0; nf < 4; nf++) {
                uint32_t vhv = qh[pb + 256 + h * 16 + nf * 4 + tg];
                uint32_t vlv = ql[pb + 256 + h * 16 + nf * 4 + tg];
                float v0 = bflo(vhv) + bflo(vlv);
                float v1 = bfhi(vhv) + bfhi(vlv);
                oacc[nf][half*2]   = oacc[nf][half*2]   * corr + p * v0;
                oacc[nf][half*2+1] = oacc[nf][half*2+1] * corr + p * v1;
            }
        }
    }

    sum0 += __shfl_xor_sync(~0u, sum0, 1);
    sum0 += __shfl_xor_sync(~0u, sum0, 2);
    sum1 += __shfl_xor_sync(~0u, sum1, 1);
    sum1 += __shfl_xor_sync(~0u, sum1, 2);
    float inv0 = 1.f / sum0, inv1 = 1.f / sum1;

    int row = q0 + warp * 16 + g;
    size_t ob0 = ((size_t)(tb + row) * 256 + h * 32) >> 1;
    size_t ob1 = ((size_t)(tb + row + 8) * 256 + h * 32) >> 1;
    #pragma unroll
    for (int nf = 0; nf < 4; nf++) {
        uint32_t hh_, ll_;
        split2(oacc[nf][0] * inv0, oacc[nf][1] * inv0, hh_, ll_);
        oh[ob0 + nf * 4 + tg] = hh_;
        ol[ob0 + nf * 4 + tg] = ll_;
        split2(oacc[nf][2] * inv1, oacc[nf][3] * inv1, hh_, ll_);
        oh[ob1 + nf * 4 + tg] = hh_;
        ol[ob1 + nf * 4 + tg] = ll_;
    }
}

// ---------------- encoder layer-1 ----------------
__global__ __launch_bounds__(128) void encode_hidden(
    const float* __restrict__ xc, const float* __restrict__ yc,
    const float* __restrict__ xt,
    const float* __restrict__ W1, const float* __restrict__ b1,
    uint32_t* __restrict__ hh, uint32_t* __restrict__ hl)
{
    int tok = blockIdx.x;
    int m = tok >> 10, t = tok & 1023;
    int tid = threadIdx.x;
    int d = tid * 2;

    __shared__ float s_in[16];
    if (tid < 10) {
        float v;
        if (tid < 8) {
            v = (t < NCC) ? xc[(m * NCC + t) * 8 + tid]
                          : xt[(m * NCC + (t - NCC)) * 8 + tid];
        } else if (tid == 8) {
            v = (t < NCC) ? yc[m * NCC + t] : 0.0f;
        } else {
            v = (t < NCC) ? 0.0f : 1.0f;
        }
        s_in[tid] = v;
    }
    __syncthreads();

    float a0 = b1[d], a1 = b1[d + 1];
    #pragma unroll
    for (int k = 0; k < 10; k++) {
        a0 += s_in[k] * W1[k * DMOD + d];
        a1 += s_in[k] * W1[k * DMOD + d + 1];
    }
    uint32_t h, l;
    split2(fmaxf(a0, 0.0f), fmaxf(a1, 0.0f), h, l);
    hh[tok * 128 + tid] = h;
    hl[tok * 128 + tid] = l;
}

// ---------------- layernorm (warp/token), split bf16 output ----------------
__global__ __launch_bounds__(256) void ln_kernel(
    const float* __restrict__ x, const float* __restrict__ g,
    const float* __restrict__ b,
    uint32_t* __restrict__ yh, uint32_t* __restrict__ yl)
{
    int tok  = (blockIdx.x * 256 + threadIdx.x) >> 5;
    int lane = threadIdx.x & 31;

    const float4* xp = (const float4*)(x + (size_t)tok * DMOD);
    float4 v0 = xp[lane * 2], v1 = xp[lane * 2 + 1];

    float s = v0.x + v0.y + v0.z + v0.w + v1.x + v1.y + v1.z + v1.w;
    #pragma unroll
    for (int o = 16; o > 0; o >>= 1) s += __shfl_xor_sync(0xffffffffu, s, o);
    float mu = s * (1.0f / DMOD);

    float d0 = v0.x - mu, d1 = v0.y - mu, d2 = v0.z - mu, d3 = v0.w - mu;
    float d4 = v1.x - mu, d5 = v1.y - mu, d6 = v1.z - mu, d7 = v1.w - mu;
    float q = d0*d0 + d1*d1 + d2*d2 + d3*d3 + d4*d4 + d5*d5 + d6*d6 + d7*d7;
    #pragma unroll
    for (int o = 16; o > 0; o >>= 1) q += __shfl_xor_sync(0xffffffffu, q, o);
    float rstd = rsqrtf(q * (1.0f / DMOD) + 1e-5f);

    const float4* gp = (const float4*)g;
    const float4* bp = (const float4*)b;
    float4 g0 = gp[lane * 2], g1 = gp[lane * 2 + 1];
    float4 b0 = bp[lane * 2], b1 = bp[lane * 2 + 1];

    float o0 = d0 * rstd * g0.x + b0.x, o1 = d1 * rstd * g0.y + b0.y;
    float o2 = d2 * rstd * g0.z + b0.z, o3 = d3 * rstd * g0.w + b0.w;
    float o4 = d4 * rstd * g1.x + b1.x, o5 = d5 * rstd * g1.y + b1.y;
    float o6 = d6 * rstd * g1.z + b1.z, o7 = d7 * rstd * g1.w + b1.w;

    uint32_t h, l;
    int base = tok * 128 + lane * 4;
    split2(o0, o1, h, l);  yh[base + 0] = h;  yl[base + 0] = l;
    split2(o2, o3, h, l);  yh[base + 1] = h;  yl[base + 1] = l;
    split2(o4, o5, h, l);  yh[base + 2] = h;  yl[base + 2] = l;
    split2(o6, o7, h, l);  yh[base + 3] = h;  yl[base + 3] = l;
}

// ---------------- launch ----------------
#define BF16P(sym) ((const __nv_bfloat16*)sym)

extern "C" void kernel_launch(void* const* d_in, const int* in_sizes, int n_in,
                              void* d_out, int out_size)
{
    const float* xc     = (const float*)d_in[0];
    const float* yc     = (const float*)d_in[1];
    const float* xt     = (const float*)d_in[2];
    const float* enc_W1 = (const float*)d_in[3];
    const float* enc_b1 = (const float*)d_in[4];
    const float* enc_W2 = (const float*)d_in[5];
    const float* enc_b2 = (const float*)d_in[6];
    const float* Wqkv   = (const float*)d_in[7];
    const float* bqkv   = (const float*)d_in[8];
    const float* Wo     = (const float*)d_in[9];
    const float* bo     = (const float*)d_in[10];
    const float* ln1_g  = (const float*)d_in[11];
    const float* ln1_b  = (const float*)d_in[12];
    const float* ln2_g  = (const float*)d_in[13];
    const float* ln2_b  = (const float*)d_in[14];
    const float* Wff1   = (const float*)d_in[15];
    const float* bff1   = (const float*)d_in[16];
    const float* Wff2   = (const float*)d_in[17];
    const float* bff2   = (const float*)d_in[18];
    float* out          = (float*)d_out;

    float* z;
    uint32_t *hh, *hl, *qkh, *qkl, *ah, *al, *fh, *fl;
    uint32_t *wqh, *wql, *woh, *wol, *w1h, *w1l, *w2h, *w2l, *ewh, *ewl;
    cudaGetSymbolAddress((void**)&z,   g_z);
    cudaGetSymbolAddress((void**)&hh,  g_h_h);   cudaGetSymbolAddress((void**)&hl,  g_h_l);
    cudaGetSymbolAddress((void**)&qkh, g_qkv_h); cudaGetSymbolAddress((void**)&qkl, g_qkv_l);
    cudaGetSymbolAddress((void**)&ah,  g_att_h); cudaGetSymbolAddress((void**)&al,  g_att_l);
    cudaGetSymbolAddress((void**)&fh,  g_ff_h);  cudaGetSymbolAddress((void**)&fl,  g_ff_l);
    cudaGetSymbolAddress((void**)&wqh, g_wqkv_h); cudaGetSymbolAddress((void**)&wql, g_wqkv_l);
    cudaGetSymbolAddress((void**)&woh, g_wo_h);   cudaGetSymbolAddress((void**)&wol, g_wo_l);
    cudaGetSymbolAddress((void**)&w1h, g_wff1_h); cudaGetSymbolAddress((void**)&w1l, g_wff1_l);
    cudaGetSymbolAddress((void**)&w2h, g_wff2_h); cudaGetSymbolAddress((void**)&w2l, g_wff2_l);
    cudaGetSymbolAddress((void**)&ewh, g_ew2_h);  cudaGetSymbolAddress((void**)&ewl, g_ew2_l);

    const int SM64 = GEMM_SMEM(64);
    cudaFuncSetAttribute(gemm_bf3<0, 64>, cudaFuncAttributeMaxDynamicSharedMemorySize, SM64);
    cudaFuncSetAttribute(gemm_bf3<1, 64>, cudaFuncAttributeMaxDynamicSharedMemorySize, SM64);
    cudaFuncSetAttribute(gemm_bf3<2, 64>, cudaFuncAttributeMaxDynamicSharedMemorySize, SM64);
    cudaFuncSetAttribute(gemm_bf3<3, 64>, cudaFuncAttributeMaxDynamicSharedMemorySize, SM64);
    cudaFuncSetAttribute(attn_mma, cudaFuncAttributeMaxDynamicSharedMemorySize, ATTN_SMEM);

    // ---- merged weight split (one launch) ----
    split_all<<<(P_TOT + 255) / 256, 256>>>(enc_W2, Wqkv, Wo, Wff1, Wff2);

    encode_hidden<<<TOK, 128>>>(xc, yc, xt, enc_W1, enc_b1, hh, hl);
    gemm_bf3<0, 64><<<dim3(DMOD / BN, TOK / 64), 256, SM64>>>(
        BF16P(hh), BF16P(hl), BF16P(ewh), BF16P(ewl),
        enc_b2, nullptr, z, nullptr, nullptr, DMOD, DMOD);

    for (int l = 0; l < NLAY; l++) {
        const uint32_t* wq_h = wqh + (size_t)l * DMOD * 3 * DMOD / 2;
        const uint32_t* wq_l = wql + (size_t)l * DMOD * 3 * DMOD / 2;
        const uint32_t* wo_h = woh + (size_t)l * DMOD * DMOD / 2;
        const uint32_t* wo_l = wol + (size_t)l * DMOD * DMOD / 2;
        const uint32_t* f1_h = w1h + (size_t)l * DMOD * FFD / 2;
        const uint32_t* f1_l = w1l + (size_t)l * DMOD * FFD / 2;
        const uint32_t* f2_h = w2h + (size_t)l * FFD * DMOD / 2;
        const uint32_t* f2_l = w2l + (size_t)l * FFD * DMOD / 2;

        ln_kernel<<<TOK / 8, 256>>>(z, ln1_g + l * DMOD, ln1_b + l * DMOD, hh, hl);
        gemm_bf3<3, 64><<<dim3(3 * DMOD / BN, TOK / 64), 256, SM64>>>(
            BF16P(hh), BF16P(hl), BF16P(wq_h), BF16P(wq_l),
            bqkv + l * 3 * DMOD, nullptr, nullptr, qkh, qkl, DMOD, 3 * DMOD);
        attn_mma<<<dim3(MB * NH, NTOK / 64), 128, ATTN_SMEM>>>(qkh, qkl, ah, al);
        gemm_bf3<1, 64><<<dim3(DMOD / BN, TOK / 64), 256, SM64>>>(
            BF16P(ah), BF16P(al), BF16P(wo_h), BF16P(wo_l),
            bo + l * DMOD, z, z, nullptr, nullptr, DMOD, DMOD);
        ln_kernel<<<TOK / 8, 256>>>(z, ln2_g + l * DMOD, ln2_b + l * DMOD, hh, hl);
        gemm_bf3<2, 64><<<dim3(FFD / BN, TOK / 64), 256, SM64>>>(
            BF16P(hh), BF16P(hl), BF16P(f1_h), BF16P(f1_l),
            bff1 + l * FFD, nullptr, nullptr, fh, fl, DMOD, FFD);
        float* dst = (l == NLAY - 1) ? out : z;
        gemm_bf3<1, 64><<<dim3(DMOD / BN, TOK / 64), 256, SM64>>>(
            BF16P(fh), BF16P(fl), BF16P(f2_h), BF16P(f2_l),
            bff2 + l * DMOD, z, dst, nullptr, nullptr, FFD, DMOD);
    }
}

// round 14
// speedup vs baseline: 1.5740x; 1.5740x over previous
#include <cuda_runtime.h>
#include <cuda_bf16.h>
#include <math.h>
#include <stdint.h>

// ---------------- problem constants ----------------
#define MB    8
#define NCC   512
#define NTOK  1024
#define DMOD  256
#define NH    8
#define NLAY  6
#define FFD   1024
#define DHD   32
#define TOK   (MB * NTOK)   // 8192

// ---------------- device scratch ----------------
__device__ float g_z[TOK * DMOD];
// split activations (bf16 hi/lo packed as uint32 pairs)
__device__ uint32_t g_h_h[TOK * DMOD / 2],  g_h_l[TOK * DMOD / 2];
__device__ uint32_t g_qkv_h[TOK * 3 * DMOD / 2], g_qkv_l[TOK * 3 * DMOD / 2];
__device__ uint32_t g_att_h[TOK * DMOD / 2], g_att_l[TOK * DMOD / 2];
__device__ uint32_t g_ff_h[TOK * FFD / 2],   g_ff_l[TOK * FFD / 2];
// split weights [K][N]
__device__ uint32_t g_wqkv_h[NLAY * DMOD * 3 * DMOD / 2], g_wqkv_l[NLAY * DMOD * 3 * DMOD / 2];
__device__ uint32_t g_wo_h[NLAY * DMOD * DMOD / 2],       g_wo_l[NLAY * DMOD * DMOD / 2];
__device__ uint32_t g_wff1_h[NLAY * DMOD * FFD / 2],      g_wff1_l[NLAY * DMOD * FFD / 2];
__device__ uint32_t g_wff2_h[NLAY * FFD * DMOD / 2],      g_wff2_l[NLAY * FFD * DMOD / 2];
__device__ uint32_t g_ew2_h[DMOD * DMOD / 2],             g_ew2_l[DMOD * DMOD / 2];

// ---------------- helpers ----------------
__device__ __forceinline__ void split2(float x0, float x1, uint32_t& h, uint32_t& l) {
    uint32_t hh;
    asm("cvt.rn.bf16x2.f32 %0, %1, %2;" : "=r"(hh) : "f"(x1), "f"(x0));
    float h0f = __uint_as_float(hh << 16);
    float h1f = __uint_as_float(hh & 0xffff0000u);
    h = hh;
    float l0 = x0 - h0f, l1 = x1 - h1f;
    asm("cvt.rn.bf16x2.f32 %0, %1, %2;" : "=r"(l) : "f"(l1), "f"(l0));
}
__device__ __forceinline__ float bflo(uint32_t v) { return __uint_as_float(v << 16); }
__device__ __forceinline__ float bfhi(uint32_t v) { return __uint_as_float(v & 0xffff0000u); }

__device__ __forceinline__ void cp_async16(void* dst, const void* src) {
    uint32_t d = (uint32_t)__cvta_generic_to_shared(dst);
    asm volatile("cp.async.cg.shared.global [%0], [%1], 16;\n" :: "r"(d), "l"(src));
}
__device__ __forceinline__ void cp_commit() { asm volatile("cp.async.commit_group;\n"); }
template <int N>
__device__ __forceinline__ void cp_wait() { asm volatile("cp.async.wait_group %0;\n" :: "n"(N)); }

__device__ __forceinline__ uint32_t smem_u32(const void* p) {
    return (uint32_t)__cvta_generic_to_shared(p);
}

#define LDM4(R0, R1, R2, R3, ADDR)                                          \
    asm volatile("ldmatrix.sync.aligned.m8n8.x4.shared.b16 {%0,%1,%2,%3}, [%4];" \
                 : "=r"(R0), "=r"(R1), "=r"(R2), "=r"(R3) : "r"(ADDR))

#define LDM4T(R0, R1, R2, R3, ADDR)                                         \
    asm volatile("ldmatrix.sync.aligned.m8n8.x4.trans.shared.b16 {%0,%1,%2,%3}, [%4];" \
                 : "=r"(R0), "=r"(R1), "=r"(R2), "=r"(R3) : "r"(ADDR))

#define MMA_BF16(ACC, A0, A1, A2, A3, B0, B1)                               \
    asm volatile(                                                           \
        "mma.sync.aligned.m16n8k16.row.col.f32.bf16.bf16.f32 "             \
        "{%0,%1,%2,%3}, {%4,%5,%6,%7}, {%8,%9}, {%0,%1,%2,%3};"            \
        : "+f"((ACC)[0]), "+f"((ACC)[1]), "+f"((ACC)[2]), "+f"((ACC)[3])   \
        : "r"(A0), "r"(A1), "r"(A2), "r"(A3), "r"(B0), "r"(B1))

// ---------------- merged weight split: fp32 -> bf16 hi/lo, all weights ----------------
#define P_EW  (DMOD * DMOD / 2)                    // 32768
#define P_QKV (NLAY * DMOD * 3 * DMOD / 2)         // 589824
#define P_WO  (NLAY * DMOD * DMOD / 2)             // 196608
#define P_FF1 (NLAY * DMOD * FFD / 2)              // 786432
#define P_FF2 (NLAY * FFD * DMOD / 2)              // 786432
#define P_TOT (P_EW + P_QKV + P_WO + P_FF1 + P_FF2)

__global__ __launch_bounds__(256) void split_all(
    const float* __restrict__ enc_W2, const float* __restrict__ Wqkv,
    const float* __restrict__ Wo, const float* __restrict__ Wff1,
    const float* __restrict__ Wff2)
{
    int i = blockIdx.x * 256 + threadIdx.x;
    if (i >= P_TOT) return;
    const float* src;
    uint32_t *hi, *lo;
    int j;
    if (i < P_EW) {
        j = i; src = enc_W2; hi = g_ew2_h; lo = g_ew2_l;
    } else if (i < P_EW + P_QKV) {
        j = i - P_EW; src = Wqkv; hi = g_wqkv_h; lo = g_wqkv_l;
    } else if (i < P_EW + P_QKV + P_WO) {
        j = i - (P_EW + P_QKV); src = Wo; hi = g_wo_h; lo = g_wo_l;
    } else if (i < P_EW + P_QKV + P_WO + P_FF1) {
        j = i - (P_EW + P_QKV + P_WO); src = Wff1; hi = g_wff1_h; lo = g_wff1_l;
    } else {
        j = i - (P_EW + P_QKV + P_WO + P_FF1); src = Wff2; hi = g_wff2_h; lo = g_wff2_l;
    }
    uint32_t h, l;
    split2(src[2 * j], src[2 * j + 1], h, l);
    hi[j] = h;
    lo[j] = l;
}

// ---------------- pure-bf16 3-pass tensor-core GEMM (256 thr, 8 warps) ----------------
// BMV=128: warp tile 64x32 (MI=4), best arithmetic intensity — for large-N gemms
// (QKV N=768, FF1 N=1024) whose grids already fill the chip.
// BMV=64: warp tile 32x32 (MI=2), ~80 regs -> 2-3 CTAs/SM — for N=256 gemms whose
// BM=128 grid (128 CTAs) under-fills 148 SMs.
#define BN 128
#define BK 32
#define AST 40    // bf16 stride (80 B rows)
#define BST 136   // bf16 stride (272 B rows)
#define ASTB 80
#define BSTB 272
#define GEMM_SMEM(BMV) ((2*(BMV)*AST + 2*BK*BST) * 2 * 2)
// BMV=128: 75776 B ; BMV=64: 55296 B

// OUTMODE: 0 fp32, 1 fp32+resid, 2 relu+split, 3 split
template <int OUTMODE, int BMV>
__global__ __launch_bounds__(256) void gemm_bf3(
    const __nv_bfloat16* __restrict__ Ah, const __nv_bfloat16* __restrict__ Al,
    const __nv_bfloat16* __restrict__ Bh, const __nv_bfloat16* __restrict__ Bl,
    const float* __restrict__ bias, const float* __restrict__ Rsd,
    float* __restrict__ C, uint32_t* __restrict__ Chi, uint32_t* __restrict__ Clo,
    int K, int N)
{
    constexpr int MI = BMV / 32;          // m16 fragments per warp
    extern __shared__ char smem_raw[];
    __nv_bfloat16* sAh = (__nv_bfloat16*)smem_raw;
    __nv_bfloat16* sAl = sAh + 2 * BMV * AST;
    __nv_bfloat16* sBh = sAl + 2 * BMV * AST;
    __nv_bfloat16* sBl = sBh + 2 * BK * BST;

    const int tid = threadIdx.x;
    const int warp = tid >> 5, lane = tid & 31;
    const int g = lane >> 2, tg = lane & 3;
    const int wy = warp >> 2, wx = warp & 3;   // 2x4 warps
    const int row0 = blockIdx.y * BMV, col0 = blockIdx.x * BN;

    float acc[MI][4][4];
    #pragma unroll
    for (int a = 0; a < MI; a++)
        #pragma unroll
        for (int b = 0; b < 4; b++)
            #pragma unroll
            for (int c = 0; c < 4; c++) acc[a][b][c] = 0.0f;

    auto issue = [&](int t, int b) {
        #pragma unroll
        for (int s = tid; s < BMV * 4; s += 256) {
            int arow = s >> 2, aseg = s & 3;
            cp_async16(sAh + b * BMV * AST + arow * AST + aseg * 8,
                       Ah + (size_t)(row0 + arow) * K + t * BK + aseg * 8);
            cp_async16(sAl + b * BMV * AST + arow * AST + aseg * 8,
                       Al + (size_t)(row0 + arow) * K + t * BK + aseg * 8);
        }
        #pragma unroll
        for (int s = tid; s < 512; s += 256) {
            int brow = s >> 4, bseg = s & 15;
            cp_async16(sBh + b * BK * BST + brow * BST + bseg * 8,
                       Bh + (size_t)(t * BK + brow) * N + col0 + bseg * 8);
            cp_async16(sBl + b * BK * BST + brow * BST + bseg * 8,
                       Bl + (size_t)(t * BK + brow) * N + col0 + bseg * 8);
        }
        cp_commit();
    };

    const int a_lane = (wy * (BMV / 2) + (lane & 15)) * ASTB + (lane >> 4) * 16;
    const int b_lane = (lane & 15) * BSTB + (lane >> 4) * 16 + wx * 64;

    auto compute = [&](int b) {
        uint32_t aHb = smem_u32(sAh + b * BMV * AST) + a_lane;
        uint32_t aLb = smem_u32(sAl + b * BMV * AST) + a_lane;
        uint32_t bHb = smem_u32(sBh + b * BK * BST) + b_lane;
        uint32_t bLb = smem_u32(sBl + b * BK * BST) + b_lane;

        #pragma unroll
        for (int ks = 0; ks < 2; ks++) {
            uint32_t ah[MI][4], al[MI][4], bh[2][4], bl[2][4];
            #pragma unroll
            for (int mi = 0; mi < MI; mi++) {
                LDM4(ah[mi][0], ah[mi][1], ah[mi][2], ah[mi][3],
                     aHb + mi * 16 * ASTB + ks * 32);
                LDM4(al[mi][0], al[mi][1], al[mi][2], al[mi][3],
                     aLb + mi * 16 * ASTB + ks * 32);
            }
            #pragma unroll
            for (int nc = 0; nc < 2; nc++) {
                LDM4T(bh[nc][0], bh[nc][1], bh[nc][2], bh[nc][3],
                      bHb + ks * 16 * BSTB + nc * 32);
                LDM4T(bl[nc][0], bl[nc][1], bl[nc][2], bl[nc][3],
                      bLb + ks * 16 * BSTB + nc * 32);
            }
            #pragma unroll
            for (int mi = 0; mi < MI; mi++)
                #pragma unroll
                for (int nf = 0; nf < 4; nf++) {
                    const int p = nf >> 1, q = (nf & 1) * 2;
                    MMA_BF16(acc[mi][nf], al[mi][0], al[mi][1], al[mi][2], al[mi][3],
                             bh[p][q], bh[p][q + 1]);
                    MMA_BF16(acc[mi][nf], ah[mi][0], ah[mi][1], ah[mi][2], ah[mi][3],
                             bl[p][q], bl[p][q + 1]);
                    MMA_BF16(acc[mi][nf], ah[mi][0], ah[mi][1], ah[mi][2], ah[mi][3],
                             bh[p][q], bh[p][q + 1]);
                }
        }
    };

    const int T = K / BK;
    issue(0, 0);
    for (int t = 0; t < T; t++) {
        const int buf = t & 1;
        if (t + 1 < T) {
            issue(t + 1, buf ^ 1);
            cp_wait<1>();
        } else {
            cp_wait<0>();
        }
        __syncthreads();
        compute(buf);
        __syncthreads();
    }

    #pragma unroll
    for (int mi = 0; mi < MI; mi++) {
        #pragma unroll
        for (int nf = 0; nf < 4; nf++) {
            const int r = row0 + wy * (BMV / 2) + mi * 16 + g;
            const int c = col0 + wx * 32 + nf * 8 + tg * 2;
            const float b0 = bias[c], b1 = bias[c + 1];
            float v0 = acc[mi][nf][0] + b0;
            float v1 = acc[mi][nf][1] + b1;
            float v2 = acc[mi][nf][2] + b0;
            float v3 = acc[mi][nf][3] + b1;
            if (OUTMODE >= 2) {
                if (OUTMODE == 2) {
                    v0 = fmaxf(v0, 0.0f); v1 = fmaxf(v1, 0.0f);
                    v2 = fmaxf(v2, 0.0f); v3 = fmaxf(v3, 0.0f);
                }
                uint32_t h, l;
                split2(v0, v1, h, l);
                Chi[((size_t)r * N + c) >> 1] = h;
                Clo[((size_t)r * N + c) >> 1] = l;
                split2(v2, v3, h, l);
                Chi[((size_t)(r + 8) * N + c) >> 1] = h;
                Clo[((size_t)(r + 8) * N + c) >> 1] = l;
            } else {
                if (OUTMODE == 1) {
                    v0 += Rsd[(size_t)r * N + c];
                    v1 += Rsd[(size_t)r * N + c + 1];
                    v2 += Rsd[(size_t)(r + 8) * N + c];
                    v3 += Rsd[(size_t)(r + 8) * N + c + 1];
                }
                *(float2*)&C[(size_t)r * N + c]       = make_float2(v0, v1);
                *(float2*)&C[(size_t)(r + 8) * N + c] = make_float2(v2, v3);
            }
        }
    }
}

// ---------------- tensor-core flash attention (R7, unchanged) ----------------
#define QST 40
#define QSTB 80
#define ATTN_SMEM ((2*64*QST + 8*64*QST) * 2)   // 51200 bytes

__global__ __launch_bounds__(128) void attn_mma(
    const uint32_t* __restrict__ qh, const uint32_t* __restrict__ ql,
    uint32_t* __restrict__ oh, uint32_t* __restrict__ ol)
{
    extern __shared__ char sm[];
    __nv_bfloat16* sQh = (__nv_bfloat16*)sm;
    __nv_bfloat16* sQl = sQh + 64 * QST;
    __nv_bfloat16* sKh = sQl + 64 * QST;
    __nv_bfloat16* sKl = sKh + 2 * 64 * QST;
    __nv_bfloat16* sVh = sKl + 2 * 64 * QST;
    __nv_bfloat16* sVl = sVh + 2 * 64 * QST;

    const int mh = blockIdx.x, qb = blockIdx.y;
    const int m = mh >> 3, h = mh & 7;
    const int q0 = qb * 64;
    const int tid = threadIdx.x, warp = tid >> 5, lane = tid & 31;
    const int g = lane >> 2, tg = lane & 3;
    const int tb = m * NTOK;
    const float scale = 0.17677669529663687f;

    const int i0 = tid * 2;
    const int lrow0 = i0 >> 2, lseg0 = i0 & 3;
    const int lrow1 = (i0 + 1) >> 2, lseg1 = (i0 + 1) & 3;

    {
        size_t s0 = (size_t)(tb + q0 + lrow0) * 384 + h * 16 + lseg0 * 4;
        size_t s1 = (size_t)(tb + q0 + lrow1) * 384 + h * 16 + lseg1 * 4;
        cp_async16(sQh + lrow0 * QST + lseg0 * 8, qh + s0);
        cp_async16(sQh + lrow1 * QST + lseg1 * 8, qh + s1);
        cp_async16(sQl + lrow0 * QST + lseg0 * 8, ql + s0);
        cp_async16(sQl + lrow1 * QST + lseg1 * 8, ql + s1);
        cp_commit();
    }
    auto issueKV = [&](int c, int b) {
        int k0 = c * 64;
        size_t s0 = (size_t)(tb + k0 + lrow0) * 384 + 128 + h * 16 + lseg0 * 4;
        size_t s1 = (size_t)(tb + k0 + lrow1) * 384 + 128 + h * 16 + lseg1 * 4;
        __nv_bfloat16* kh = sKh + b * 64 * QST;
        __nv_bfloat16* kl = sKl + b * 64 * QST;
        __nv_bfloat16* vh = sVh + b * 64 * QST;
        __nv_bfloat16* vl = sVl + b * 64 * QST;
        cp_async16(kh + lrow0 * QST + lseg0 * 8, qh + s0);
        cp_async16(kh + lrow1 * QST + lseg1 * 8, qh + s1);
        cp_async16(kl + lrow0 * QST + lseg0 * 8, ql + s0);
        cp_async16(kl + lrow1 * QST + lseg1 * 8, ql + s1);
        cp_async16(vh + lrow0 * QST + lseg0 * 8, qh + s0 + 128);
        cp_async16(vh + lrow1 * QST + lseg1 * 8, qh + s1 + 128);
        cp_async16(vl + lrow0 * QST + lseg0 * 8, ql + s0 + 128);
        cp_async16(vl + lrow1 * QST + lseg1 * 8, ql + s1 + 128);
        cp_commit();
    };

    issueKV(0, 0);
    cp_wait<1>();
    __syncthreads();

    uint32_t qfh[2][4], qfl[2][4];
    {
        uint32_t bh_ = smem_u32(sQh) + (warp * 16 + (lane & 15)) * QSTB + (lane >> 4) * 16;
        uint32_t bl_ = smem_u32(sQl) + (warp * 16 + (lane & 15)) * QSTB + (lane >> 4) * 16;
        LDM4(qfh[0][0], qfh[0][1], qfh[0][2], qfh[0][3], bh_);
        LDM4(qfh[1][0], qfh[1][1], qfh[1][2], qfh[1][3], bh_ + 32);
        LDM4(qfl[0][0], qfl[0][1], qfl[0][2], qfl[0][3], bl_);
        LDM4(qfl[1][0], qfl[1][1], qfl[1][2], qfl[1][3], bl_ + 32);
    }

    float mx0 = -1e30f, mx1 = -1e30f, sum0 = 0.f, sum1 = 0.f;
    float oacc[4][4];
    #pragma unroll
    for (int a = 0; a < 4; a++)
        #pragma unroll
        for (int b = 0; b < 4; b++) oacc[a][b] = 0.f;

    const uint32_t kbyte = ((lane & 7) + ((lane >> 4) & 1) * 8) * QSTB +
                           ((lane >> 3) & 1) * 16;
    const uint32_t vbyte = (lane & 15) * QSTB + (lane >> 4) * 16;

    for (int c = 0; c < 8; c++) {
        const int b = c & 1;
        if (c + 1 < 8) { issueKV(c + 1, b ^ 1); cp_wait<1>(); }
        else           { cp_wait<0>(); }
        __syncthreads();

        uint32_t khb = smem_u32(sKh + b * 64 * QST) + kbyte;
        uint32_t klb = smem_u32(sKl + b * 64 * QST) + kbyte;

        float sacc[8][4];
        #pragma unroll
        for (int a = 0; a < 8; a++)
            #pragma unroll
            for (int j = 0; j < 4; j++) sacc[a][j] = 0.f;

        #pragma unroll
        for (int nk = 0; nk < 4; nk++) {
            uint32_t kh0[4], kh1[4], kl0[4], kl1[4];
            LDM4(kh0[0], kh0[1], kh0[2], kh0[3], khb + nk * 16 * QSTB);
            LDM4(kh1[0], kh1[1], kh1[2], kh1[3], khb + nk * 16 * QSTB + 32);
            LDM4(kl0[0], kl0[1], kl0[2], kl0[3], klb + nk * 16 * QSTB);
            LDM4(kl1[0], kl1[1], kl1[2], kl1[3], klb + nk * 16 * QSTB + 32);
            MMA_BF16(sacc[nk*2], qfl[0][0], qfl[0][1], qfl[0][2], qfl[0][3], kh0[0], kh0[1]);
            MMA_BF16(sacc[nk*2], qfl[1][0], qfl[1][1], qfl[1][2], qfl[1][3], kh1[0], kh1[1]);
            MMA_BF16(sacc[nk*2], qfh[0][0], qfh[0][1], qfh[0][2], qfh[0][3], kl0[0], kl0[1]);
            MMA_BF16(sacc[nk*2], qfh[1][0], qfh[1][1], qfh[1][2], qfh[1][3], kl1[0], kl1[1]);
            MMA_BF16(sacc[nk*2], qfh[0][0], qfh[0][1], qfh[0][2], qfh[0][3], kh0[0], kh0[1]);
            MMA_BF16(sacc[nk*2], qfh[1][0], qfh[1][1], qfh[1][2], qfh[1][3], kh1[0], kh1[1]);
            MMA_BF16(sacc[nk*2+1], qfl[0][0], qfl[0][1], qfl[0][2], qfl[0][3], kh0[2], kh0[3]);
            MMA_BF16(sacc[nk*2+1], qfl[1][0], qfl[1][1], qfl[1][2], qfl[1][3], kh1[2], kh1[3]);
            MMA_BF16(sacc[nk*2+1], qfh[0][0], qfh[0][1], qfh[0][2], qfh[0][3], kl0[2], kl0[3]);
            MMA_BF16(sacc[nk*2+1], qfh[1][0], qfh[1][1], qfh[1][2], qfh[1][3], kl1[2], kl1[3]);
            MMA_BF16(sacc[nk*2+1], qfh[0][0], qfh[0][1], qfh[0][2], qfh[0][3], kh0[2], kh0[3]);
            MMA_BF16(sacc[nk*2+1], qfh[1][0], qfh[1][1], qfh[1][2], qfh[1][3], kh1[2], kh1[3]);
        }

        float cm0 = -1e30f, cm1 = -1e30f;
        #pragma unroll
        for (int a = 0; a < 8; a++) {
            #pragma unroll
            for (int j = 0; j < 4; j++) sacc[a][j] *= scale;
            cm0 = fmaxf(cm0, fmaxf(sacc[a][0], sacc[a][1]));
            cm1 = fmaxf(cm1, fmaxf(sacc[a][2], sacc[a][3]));
        }
        cm0 = fmaxf(cm0, __shfl_xor_sync(~0u, cm0, 1));
        cm0 = fmaxf(cm0, __shfl_xor_sync(~0u, cm0, 2));
        cm1 = fmaxf(cm1, __shfl_xor_sync(~0u, cm1, 1));
        cm1 = fmaxf(cm1, __shfl_xor_sync(~0u, cm1, 2));
        float nm0 = fmaxf(mx0, cm0), nm1 = fmaxf(mx1, cm1);
        float c0 = __expf(mx0 - nm0), c1 = __expf(mx1 - nm1);
        sum0 *= c0; sum1 *= c1;
        #pragma unroll
        for (int a = 0; a < 4; a++) {
            oacc[a][0] *= c0; oacc[a][1] *= c0;
            oacc[a][2] *= c1; oacc[a][3] *= c1;
        }
        #pragma unroll
        for (int a = 0; a < 8; a++) {
            sacc[a][0] = __expf(sacc[a][0] - nm0);
            sacc[a][1] = __expf(sacc[a][1] - nm0);
            sacc[a][2] = __expf(sacc[a][2] - nm1);
            sacc[a][3] = __expf(sacc[a][3] - nm1);
            sum0 += sacc[a][0] + sacc[a][1];
            sum1 += sacc[a][2] + sacc[a][3];
        }
        mx0 = nm0; mx1 = nm1;

        uint32_t pah[4][4], pal[4][4];
        #pragma unroll
        for (int kf = 0; kf < 4; kf++) {
            split2(sacc[kf*2][0],   sacc[kf*2][1],   pah[kf][0], pal[kf][0]);
            split2(sacc[kf*2][2],   sacc[kf*2][3],   pah[kf][1], pal[kf][1]);
            split2(sacc[kf*2+1][0], sacc[kf*2+1][1], pah[kf][2], pal[kf][2]);
            split2(sacc[kf*2+1][2], sacc[kf*2+1][3], pah[kf][3], pal[kf][3]);
        }

        uint32_t vhb = smem_u32(sVh + b * 64 * QST) + vbyte;
        uint32_t vlb = smem_u32(sVl + b * 64 * QST) + vbyte;
        #pragma unroll
        for (int nc = 0; nc < 2; nc++) {
            #pragma unroll
            for (int kf = 0; kf < 4; kf++) {
                uint32_t vh_[4], vl_[4];
                LDM4T(vh_[0], vh_[1], vh_[2], vh_[3], vhb + kf * 16 * QSTB + nc * 32);
                LDM4T(vl_[0], vl_[1], vl_[2], vl_[3], vlb + kf * 16 * QSTB + nc * 32);
                MMA_BF16(oacc[nc*2], pal[kf][0], pal[kf][1], pal[kf][2], pal[kf][3], vh_[0], vh_[1]);
                MMA_BF16(oacc[nc*2], pah[kf][0], pah[kf][1], pah[kf][2], pah[kf][3], vl_[0], vl_[1]);
                MMA_BF16(oacc[nc*2], pah[kf][0], pah[kf][1], pah[kf][2], pah[kf][3], vh_[0], vh_[1]);
                MMA_BF16(oacc[nc*2+1], pal[kf][0], pal[kf][1], pal[kf][2], pal[kf][3], vh_[2], vh_[3]);
                MMA_BF16(oacc[nc*2+1], pah[kf][0], pah[kf][1], pah[kf][2], pah[kf][3], vl_[2], vl_[3]);
                MMA_BF16(oacc[nc*2+1], pah[kf][0], pah[kf][1], pah[kf][2], pah[kf][3], vh_[2], vh_[3]);
            }
        }
        __syncthreads();
    }

    if (q0 >= NCC) {
        #pragma unroll
        for (int half = 0; half < 2; half++) {
            int row = q0 + warp * 16 + g + half * 8;
            size_t pb = (size_t)(tb + row) * 384;
            float dot = 0.f;
            #pragma unroll
            for (int w = 0; w < 4; w++) {
                uint32_t qhv = qh[pb + h * 16 + tg * 4 + w];
                uint32_t qlv = ql[pb + h * 16 + tg * 4 + w];
                uint32_t khv = qh[pb + 128 + h * 16 + tg * 4 + w];
                uint32_t klv = ql[pb + 128 + h * 16 + tg * 4 + w];
                float qa = bflo(qhv) + bflo(qlv), qb_ = bfhi(qhv) + bfhi(qlv);
                float ka = bflo(khv) + bflo(klv), kb = bfhi(khv) + bfhi(klv);
                dot += qa * ka + qb_ * kb;
            }
            dot += __shfl_xor_sync(~0u, dot, 1);
            dot += __shfl_xor_sync(~0u, dot, 2);
            float s = dot * scale;
            float mxv = half ? mx1 : mx0;
            float nm = fmaxf(mxv, s);
            float corr = __expf(mxv - nm);
            float p = __expf(s - nm);
            if (half) { sum1 = sum1 * corr + (tg == 0 ? p : 0.f); mx1 = nm; }
            else      { sum0 = sum0 * corr + (tg == 0 ? p : 0.f); mx0 = nm; }
            #pragma unroll
            for (int nf = 0; nf < 4; nf++) {
                uint32_t vhv = qh[pb + 256 + h * 16 + nf * 4 + tg];
                uint32_t vlv = ql[pb + 256 + h * 16 + nf * 4 + tg];
                float v0 = bflo(vhv) + bflo(vlv);
                float v1 = bfhi(vhv) + bfhi(vlv);
                oacc[nf][half*2]   = oacc[nf][half*2]   * corr + p * v0;
                oacc[nf][half*2+1] = oacc[nf][half*2+1] * corr + p * v1;
            }
        }
    }

    sum0 += __shfl_xor_sync(~0u, sum0, 1);
    sum0 += __shfl_xor_sync(~0u, sum0, 2);
    sum1 += __shfl_xor_sync(~0u, sum1, 1);
    sum1 += __shfl_xor_sync(~0u, sum1, 2);
    float inv0 = 1.f / sum0, inv1 = 1.f / sum1;

    int row = q0 + warp * 16 + g;
    size_t ob0 = ((size_t)(tb + row) * 256 + h * 32) >> 1;
    size_t ob1 = ((size_t)(tb + row + 8) * 256 + h * 32) >> 1;
    #pragma unroll
    for (int nf = 0; nf < 4; nf++) {
        uint32_t hh_, ll_;
        split2(oacc[nf][0] * inv0, oacc[nf][1] * inv0, hh_, ll_);
        oh[ob0 + nf * 4 + tg] = hh_;
        ol[ob0 + nf * 4 + tg] = ll_;
        split2(oacc[nf][2] * inv1, oacc[nf][3] * inv1, hh_, ll_);
        oh[ob1 + nf * 4 + tg] = hh_;
        ol[ob1 + nf * 4 + tg] = ll_;
    }
}

// ---------------- encoder layer-1 ----------------
__global__ __launch_bounds__(128) void encode_hidden(
    const float* __restrict__ xc, const float* __restrict__ yc,
    const float* __restrict__ xt,
    const float* __restrict__ W1, const float* __restrict__ b1,
    uint32_t* __restrict__ hh, uint32_t* __restrict__ hl)
{
    int tok = blockIdx.x;
    int m = tok >> 10, t = tok & 1023;
    int tid = threadIdx.x;
    int d = tid * 2;

    __shared__ float s_in[16];
    if (tid < 10) {
        float v;
        if (tid < 8) {
            v = (t < NCC) ? xc[(m * NCC + t) * 8 + tid]
                          : xt[(m * NCC + (t - NCC)) * 8 + tid];
        } else if (tid == 8) {
            v = (t < NCC) ? yc[m * NCC + t] : 0.0f;
        } else {
            v = (t < NCC) ? 0.0f : 1.0f;
        }
        s_in[tid] = v;
    }
    __syncthreads();

    float a0 = b1[d], a1 = b1[d + 1];
    #pragma unroll
    for (int k = 0; k < 10; k++) {
        a0 += s_in[k] * W1[k * DMOD + d];
        a1 += s_in[k] * W1[k * DMOD + d + 1];
    }
    uint32_t h, l;
    split2(fmaxf(a0, 0.0f), fmaxf(a1, 0.0f), h, l);
    hh[tok * 128 + tid] = h;
    hl[tok * 128 + tid] = l;
}

// ---------------- layernorm (warp/token), split bf16 output ----------------
__global__ __launch_bounds__(256) void ln_kernel(
    const float* __restrict__ x, const float* __restrict__ g,
    const float* __restrict__ b,
    uint32_t* __restrict__ yh, uint32_t* __restrict__ yl)
{
    int tok  = (blockIdx.x * 256 + threadIdx.x) >> 5;
    int lane = threadIdx.x & 31;

    const float4* xp = (const float4*)(x + (size_t)tok * DMOD);
    float4 v0 = xp[lane * 2], v1 = xp[lane * 2 + 1];

    float s = v0.x + v0.y + v0.z + v0.w + v1.x + v1.y + v1.z + v1.w;
    #pragma unroll
    for (int o = 16; o > 0; o >>= 1) s += __shfl_xor_sync(0xffffffffu, s, o);
    float mu = s * (1.0f / DMOD);

    float d0 = v0.x - mu, d1 = v0.y - mu, d2 = v0.z - mu, d3 = v0.w - mu;
    float d4 = v1.x - mu, d5 = v1.y - mu, d6 = v1.z - mu, d7 = v1.w - mu;
    float q = d0*d0 + d1*d1 + d2*d2 + d3*d3 + d4*d4 + d5*d5 + d6*d6 + d7*d7;
    #pragma unroll
    for (int o = 16; o > 0; o >>= 1) q += __shfl_xor_sync(0xffffffffu, q, o);
    float rstd = rsqrtf(q * (1.0f / DMOD) + 1e-5f);

    const float4* gp = (const float4*)g;
    const float4* bp = (const float4*)b;
    float4 g0 = gp[lane * 2], g1 = gp[lane * 2 + 1];
    float4 b0 = bp[lane * 2], b1 = bp[lane * 2 + 1];

    float o0 = d0 * rstd * g0.x + b0.x, o1 = d1 * rstd * g0.y + b0.y;
    float o2 = d2 * rstd * g0.z + b0.z, o3 = d3 * rstd * g0.w + b0.w;
    float o4 = d4 * rstd * g1.x + b1.x, o5 = d5 * rstd * g1.y + b1.y;
    float o6 = d6 * rstd * g1.z + b1.z, o7 = d7 * rstd * g1.w + b1.w;

    uint32_t h, l;
    int base = tok * 128 + lane * 4;
    split2(o0, o1, h, l);  yh[base + 0] = h;  yl[base + 0] = l;
    split2(o2, o3, h, l);  yh[base + 1] = h;  yl[base + 1] = l;
    split2(o4, o5, h, l);  yh[base + 2] = h;  yl[base + 2] = l;
    split2(o6, o7, h, l);  yh[base + 3] = h;  yl[base + 3] = l;
}

// ---------------- launch ----------------
#define BF16P(sym) ((const __nv_bfloat16*)sym)

extern "C" void kernel_launch(void* const* d_in, const int* in_sizes, int n_in,
                              void* d_out, int out_size)
{
    const float* xc     = (const float*)d_in[0];
    const float* yc     = (const float*)d_in[1];
    const float* xt     = (const float*)d_in[2];
    const float* enc_W1 = (const float*)d_in[3];
    const float* enc_b1 = (const float*)d_in[4];
    const float* enc_W2 = (const float*)d_in[5];
    const float* enc_b2 = (const float*)d_in[6];
    const float* Wqkv   = (const float*)d_in[7];
    const float* bqkv   = (const float*)d_in[8];
    const float* Wo     = (const float*)d_in[9];
    const float* bo     = (const float*)d_in[10];
    const float* ln1_g  = (const float*)d_in[11];
    const float* ln1_b  = (const float*)d_in[12];
    const float* ln2_g  = (const float*)d_in[13];
    const float* ln2_b  = (const float*)d_in[14];
    const float* Wff1   = (const float*)d_in[15];
    const float* bff1   = (const float*)d_in[16];
    const float* Wff2   = (const float*)d_in[17];
    const float* bff2   = (const float*)d_in[18];
    float* out          = (float*)d_out;

    float* z;
    uint32_t *hh, *hl, *qkh, *qkl, *ah, *al, *fh, *fl;
    uint32_t *wqh, *wql, *woh, *wol, *w1h, *w1l, *w2h, *w2l, *ewh, *ewl;
    cudaGetSymbolAddress((void**)&z,   g_z);
    cudaGetSymbolAddress((void**)&hh,  g_h_h);   cudaGetSymbolAddress((void**)&hl,  g_h_l);
    cudaGetSymbolAddress((void**)&qkh, g_qkv_h); cudaGetSymbolAddress((void**)&qkl, g_qkv_l);
    cudaGetSymbolAddress((void**)&ah,  g_att_h); cudaGetSymbolAddress((void**)&al,  g_att_l);
    cudaGetSymbolAddress((void**)&fh,  g_ff_h);  cudaGetSymbolAddress((void**)&fl,  g_ff_l);
    cudaGetSymbolAddress((void**)&wqh, g_wqkv_h); cudaGetSymbolAddress((void**)&wql, g_wqkv_l);
    cudaGetSymbolAddress((void**)&woh, g_wo_h);   cudaGetSymbolAddress((void**)&wol, g_wo_l);
    cudaGetSymbolAddress((void**)&w1h, g_wff1_h); cudaGetSymbolAddress((void**)&w1l, g_wff1_l);
    cudaGetSymbolAddress((void**)&w2h, g_wff2_h); cudaGetSymbolAddress((void**)&w2l, g_wff2_l);
    cudaGetSymbolAddress((void**)&ewh, g_ew2_h);  cudaGetSymbolAddress((void**)&ewl, g_ew2_l);

    const int SM128 = GEMM_SMEM(128);
    const int SM64  = GEMM_SMEM(64);
    cudaFuncSetAttribute(gemm_bf3<0, 64>,  cudaFuncAttributeMaxDynamicSharedMemorySize, SM64);
    cudaFuncSetAttribute(gemm_bf3<1, 64>,  cudaFuncAttributeMaxDynamicSharedMemorySize, SM64);
    cudaFuncSetAttribute(gemm_bf3<2, 128>, cudaFuncAttributeMaxDynamicSharedMemorySize, SM128);
    cudaFuncSetAttribute(gemm_bf3<3, 128>, cudaFuncAttributeMaxDynamicSharedMemorySize, SM128);
    cudaFuncSetAttribute(attn_mma, cudaFuncAttributeMaxDynamicSharedMemorySize, ATTN_SMEM);

    // ---- merged weight split (one launch) ----
    split_all<<<(P_TOT + 255) / 256, 256>>>(enc_W2, Wqkv, Wo, Wff1, Wff2);

    encode_hidden<<<TOK, 128>>>(xc, yc, xt, enc_W1, enc_b1, hh, hl);
    gemm_bf3<0, 64><<<dim3(DMOD / BN, TOK / 64), 256, SM64>>>(
        BF16P(hh), BF16P(hl), BF16P(ewh), BF16P(ewl),
        enc_b2, nullptr, z, nullptr, nullptr, DMOD, DMOD);

    for (int l = 0; l < NLAY; l++) {
        const uint32_t* wq_h = wqh + (size_t)l * DMOD * 3 * DMOD / 2;
        const uint32_t* wq_l = wql + (size_t)l * DMOD * 3 * DMOD / 2;
        const uint32_t* wo_h = woh + (size_t)l * DMOD * DMOD / 2;
        const uint32_t* wo_l = wol + (size_t)l * DMOD * DMOD / 2;
        const uint32_t* f1_h = w1h + (size_t)l * DMOD * FFD / 2;
        const uint32_t* f1_l = w1l + (size_t)l * DMOD * FFD / 2;
        const uint32_t* f2_h = w2h + (size_t)l * FFD * DMOD / 2;
        const uint32_t* f2_l = w2l + (size_t)l * FFD * DMOD / 2;

        ln_kernel<<<TOK / 8, 256>>>(z, ln1_g + l * DMOD, ln1_b + l * DMOD, hh, hl);
        gemm_bf3<3, 128><<<dim3(3 * DMOD / BN, TOK / 128), 256, SM128>>>(
            BF16P(hh), BF16P(hl), BF16P(wq_h), BF16P(wq_l),
            bqkv + l * 3 * DMOD, nullptr, nullptr, qkh, qkl, DMOD, 3 * DMOD);
        attn_mma<<<dim3(MB * NH, NTOK / 64), 128, ATTN_SMEM>>>(qkh, qkl, ah, al);
        gemm_bf3<1, 64><<<dim3(DMOD / BN, TOK / 64), 256, SM64>>>(
            BF16P(ah), BF16P(al), BF16P(wo_h), BF16P(wo_l),
            bo + l * DMOD, z, z, nullptr, nullptr, DMOD, DMOD);
        ln_kernel<<<TOK / 8, 256>>>(z, ln2_g + l * DMOD, ln2_b + l * DMOD, hh, hl);
        gemm_bf3<2, 128><<<dim3(FFD / BN, TOK / 128), 256, SM128>>>(
            BF16P(hh), BF16P(hl), BF16P(f1_h), BF16P(f1_l),
            bff1 + l * FFD, nullptr, nullptr, fh, fl, DMOD, FFD);
        float* dst = (l == NLAY - 1) ? out : z;
        gemm_bf3<1, 64><<<dim3(DMOD / BN, TOK / 64), 256, SM64>>>(
            BF16P(fh), BF16P(fl), BF16P(f2_h), BF16P(f2_l),
            bff2 + l * DMOD, z, dst, nullptr, nullptr, FFD, DMOD);
    }
}

// round 16
// speedup vs baseline: 1.5951x; 1.0134x over previous
#include <cuda_runtime.h>
#include <cuda_bf16.h>
#include <math.h>
#include <stdint.h>

// ---------------- problem constants ----------------
#define MB    8
#define NCC   512
#define NTOK  1024
#define DMOD  256
#define NH    8
#define NLAY  6
#define FFD   1024
#define DHD   32
#define TOK   (MB * NTOK)   // 8192

// ---------------- device scratch ----------------
__device__ float g_z[TOK * DMOD];
__device__ uint32_t g_h_h[TOK * DMOD / 2],  g_h_l[TOK * DMOD / 2];
__device__ uint32_t g_qkv_h[TOK * 3 * DMOD / 2], g_qkv_l[TOK * 3 * DMOD / 2];
__device__ uint32_t g_att_h[TOK * DMOD / 2], g_att_l[TOK * DMOD / 2];
__device__ uint32_t g_ff_h[TOK * FFD / 2],   g_ff_l[TOK * FFD / 2];
__device__ uint32_t g_wqkv_h[NLAY * DMOD * 3 * DMOD / 2], g_wqkv_l[NLAY * DMOD * 3 * DMOD / 2];
__device__ uint32_t g_wo_h[NLAY * DMOD * DMOD / 2],       g_wo_l[NLAY * DMOD * DMOD / 2];
__device__ uint32_t g_wff1_h[NLAY * DMOD * FFD / 2],      g_wff1_l[NLAY * DMOD * FFD / 2];
__device__ uint32_t g_wff2_h[NLAY * FFD * DMOD / 2],      g_wff2_l[NLAY * FFD * DMOD / 2];
__device__ uint32_t g_ew2_h[DMOD * DMOD / 2],             g_ew2_l[DMOD * DMOD / 2];

// ---------------- helpers ----------------
__device__ __forceinline__ void split2(float x0, float x1, uint32_t& h, uint32_t& l) {
    uint32_t hh;
    asm("cvt.rn.bf16x2.f32 %0, %1, %2;" : "=r"(hh) : "f"(x1), "f"(x0));
    float h0f = __uint_as_float(hh << 16);
    float h1f = __uint_as_float(hh & 0xffff0000u);
    h = hh;
    float l0 = x0 - h0f, l1 = x1 - h1f;
    asm("cvt.rn.bf16x2.f32 %0, %1, %2;" : "=r"(l) : "f"(l1), "f"(l0));
}
__device__ __forceinline__ float bflo(uint32_t v) { return __uint_as_float(v << 16); }
__device__ __forceinline__ float bfhi(uint32_t v) { return __uint_as_float(v & 0xffff0000u); }

__device__ __forceinline__ void cp_async16(void* dst, const void* src) {
    uint32_t d = (uint32_t)__cvta_generic_to_shared(dst);
    asm volatile("cp.async.cg.shared.global [%0], [%1], 16;\n" :: "r"(d), "l"(src));
}
__device__ __forceinline__ void cp_commit() { asm volatile("cp.async.commit_group;\n"); }
template <int N>
__device__ __forceinline__ void cp_wait() { asm volatile("cp.async.wait_group %0;\n" :: "n"(N)); }

__device__ __forceinline__ uint32_t smem_u32(const void* p) {
    return (uint32_t)__cvta_generic_to_shared(p);
}

#define LDM4(R0, R1, R2, R3, ADDR)                                          \
    asm volatile("ldmatrix.sync.aligned.m8n8.x4.shared.b16 {%0,%1,%2,%3}, [%4];" \
                 : "=r"(R0), "=r"(R1), "=r"(R2), "=r"(R3) : "r"(ADDR))

#define LDM4T(R0, R1, R2, R3, ADDR)                                         \
    asm volatile("ldmatrix.sync.aligned.m8n8.x4.trans.shared.b16 {%0,%1,%2,%3}, [%4];" \
                 : "=r"(R0), "=r"(R1), "=r"(R2), "=r"(R3) : "r"(ADDR))

#define MMA_BF16(ACC, A0, A1, A2, A3, B0, B1)                               \
    asm volatile(                                                           \
        "mma.sync.aligned.m16n8k16.row.col.f32.bf16.bf16.f32 "             \
        "{%0,%1,%2,%3}, {%4,%5,%6,%7}, {%8,%9}, {%0,%1,%2,%3};"            \
        : "+f"((ACC)[0]), "+f"((ACC)[1]), "+f"((ACC)[2]), "+f"((ACC)[3])   \
        : "r"(A0), "r"(A1), "r"(A2), "r"(A3), "r"(B0), "r"(B1))

// ---------------- merged weight split ----------------
#define P_EW  (DMOD * DMOD / 2)
#define P_QKV (NLAY * DMOD * 3 * DMOD / 2)
#define P_WO  (NLAY * DMOD * DMOD / 2)
#define P_FF1 (NLAY * DMOD * FFD / 2)
#define P_FF2 (NLAY * FFD * DMOD / 2)
#define P_TOT (P_EW + P_QKV + P_WO + P_FF1 + P_FF2)

__global__ __launch_bounds__(256) void split_all(
    const float* __restrict__ enc_W2, const float* __restrict__ Wqkv,
    const float* __restrict__ Wo, const float* __restrict__ Wff1,
    const float* __restrict__ Wff2)
{
    int i = blockIdx.x * 256 + threadIdx.x;
    if (i >= P_TOT) return;
    const float* src;
    uint32_t *hi, *lo;
    int j;
    if (i < P_EW) {
        j = i; src = enc_W2; hi = g_ew2_h; lo = g_ew2_l;
    } else if (i < P_EW + P_QKV) {
        j = i - P_EW; src = Wqkv; hi = g_wqkv_h; lo = g_wqkv_l;
    } else if (i < P_EW + P_QKV + P_WO) {
        j = i - (P_EW + P_QKV); src = Wo; hi = g_wo_h; lo = g_wo_l;
    } else if (i < P_EW + P_QKV + P_WO + P_FF1) {
        j = i - (P_EW + P_QKV + P_WO); src = Wff1; hi = g_wff1_h; lo = g_wff1_l;
    } else {
        j = i - (P_EW + P_QKV + P_WO + P_FF1); src = Wff2; hi = g_wff2_h; lo = g_wff2_l;
    }
    uint32_t h, l;
    split2(src[2 * j], src[2 * j + 1], h, l);
    hi[j] = h;
    lo[j] = l;
}

// ---------------- generic bf16x3 GEMM (R9 shapes) ----------------
#define BN 128
#define BK 32
#define AST 40
#define BST 136
#define ASTB 80
#define BSTB 272
#define GEMM_SMEM(BMV) ((2*(BMV)*AST + 2*BK*BST) * 2 * 2)

// OUTMODE: 1 fp32+resid, 2 relu+split, 3 split
template <int OUTMODE, int BMV>
__global__ __launch_bounds__(256) void gemm_bf3(
    const __nv_bfloat16* __restrict__ Ah, const __nv_bfloat16* __restrict__ Al,
    const __nv_bfloat16* __restrict__ Bh, const __nv_bfloat16* __restrict__ Bl,
    const float* __restrict__ bias, const float* __restrict__ Rsd,
    float* __restrict__ C, uint32_t* __restrict__ Chi, uint32_t* __restrict__ Clo,
    int K, int N)
{
    constexpr int MI = BMV / 32;
    extern __shared__ char smem_raw[];
    __nv_bfloat16* sAh = (__nv_bfloat16*)smem_raw;
    __nv_bfloat16* sAl = sAh + 2 * BMV * AST;
    __nv_bfloat16* sBh = sAl + 2 * BMV * AST;
    __nv_bfloat16* sBl = sBh + 2 * BK * BST;

    const int tid = threadIdx.x;
    const int warp = tid >> 5, lane = tid & 31;
    const int g = lane >> 2, tg = lane & 3;
    const int wy = warp >> 2, wx = warp & 3;
    const int row0 = blockIdx.y * BMV, col0 = blockIdx.x * BN;

    float acc[MI][4][4];
    #pragma unroll
    for (int a = 0; a < MI; a++)
        #pragma unroll
        for (int b = 0; b < 4; b++)
            #pragma unroll
            for (int c = 0; c < 4; c++) acc[a][b][c] = 0.0f;

    auto issue = [&](int t, int b) {
        #pragma unroll
        for (int s = tid; s < BMV * 4; s += 256) {
            int arow = s >> 2, aseg = s & 3;
            cp_async16(sAh + b * BMV * AST + arow * AST + aseg * 8,
                       Ah + (size_t)(row0 + arow) * K + t * BK + aseg * 8);
            cp_async16(sAl + b * BMV * AST + arow * AST + aseg * 8,
                       Al + (size_t)(row0 + arow) * K + t * BK + aseg * 8);
        }
        #pragma unroll
        for (int s = tid; s < 512; s += 256) {
            int brow = s >> 4, bseg = s & 15;
            cp_async16(sBh + b * BK * BST + brow * BST + bseg * 8,
                       Bh + (size_t)(t * BK + brow) * N + col0 + bseg * 8);
            cp_async16(sBl + b * BK * BST + brow * BST + bseg * 8,
                       Bl + (size_t)(t * BK + brow) * N + col0 + bseg * 8);
        }
        cp_commit();
    };

    const int a_lane = (wy * (BMV / 2) + (lane & 15)) * ASTB + (lane >> 4) * 16;
    const int b_lane = (lane & 15) * BSTB + (lane >> 4) * 16 + wx * 64;

    auto compute = [&](int b) {
        uint32_t aHb = smem_u32(sAh + b * BMV * AST) + a_lane;
        uint32_t aLb = smem_u32(sAl + b * BMV * AST) + a_lane;
        uint32_t bHb = smem_u32(sBh + b * BK * BST) + b_lane;
        uint32_t bLb = smem_u32(sBl + b * BK * BST) + b_lane;

        #pragma unroll
        for (int ks = 0; ks < 2; ks++) {
            uint32_t ah[MI][4], al[MI][4], bh[2][4], bl[2][4];
            #pragma unroll
            for (int mi = 0; mi < MI; mi++) {
                LDM4(ah[mi][0], ah[mi][1], ah[mi][2], ah[mi][3],
                     aHb + mi * 16 * ASTB + ks * 32);
                LDM4(al[mi][0], al[mi][1], al[mi][2], al[mi][3],
                     aLb + mi * 16 * ASTB + ks * 32);
            }
            #pragma unroll
            for (int nc = 0; nc < 2; nc++) {
                LDM4T(bh[nc][0], bh[nc][1], bh[nc][2], bh[nc][3],
                      bHb + ks * 16 * BSTB + nc * 32);
                LDM4T(bl[nc][0], bl[nc][1], bl[nc][2], bl[nc][3],
                      bLb + ks * 16 * BSTB + nc * 32);
            }
            #pragma unroll
            for (int mi = 0; mi < MI; mi++)
                #pragma unroll
                for (int nf = 0; nf < 4; nf++) {
                    const int p = nf >> 1, q = (nf & 1) * 2;
                    MMA_BF16(acc[mi][nf], al[mi][0], al[mi][1], al[mi][2], al[mi][3],
                             bh[p][q], bh[p][q + 1]);
                    MMA_BF16(acc[mi][nf], ah[mi][0], ah[mi][1], ah[mi][2], ah[mi][3],
                             bl[p][q], bl[p][q + 1]);
                    MMA_BF16(acc[mi][nf], ah[mi][0], ah[mi][1], ah[mi][2], ah[mi][3],
                             bh[p][q], bh[p][q + 1]);
                }
        }
    };

    const int T = K / BK;
    issue(0, 0);
    for (int t = 0; t < T; t++) {
        const int buf = t & 1;
        if (t + 1 < T) {
            issue(t + 1, buf ^ 1);
            cp_wait<1>();
        } else {
            cp_wait<0>();
        }
        __syncthreads();
        compute(buf);
        __syncthreads();
    }

    #pragma unroll
    for (int mi = 0; mi < MI; mi++) {
        #pragma unroll
        for (int nf = 0; nf < 4; nf++) {
            const int r = row0 + wy * (BMV / 2) + mi * 16 + g;
            const int c = col0 + wx * 32 + nf * 8 + tg * 2;
            const float b0 = bias[c], b1 = bias[c + 1];
            float v0 = acc[mi][nf][0] + b0;
            float v1 = acc[mi][nf][1] + b1;
            float v2 = acc[mi][nf][2] + b0;
            float v3 = acc[mi][nf][3] + b1;
            if (OUTMODE >= 2) {
                if (OUTMODE == 2) {
                    v0 = fmaxf(v0, 0.0f); v1 = fmaxf(v1, 0.0f);
                    v2 = fmaxf(v2, 0.0f); v3 = fmaxf(v3, 0.0f);
                }
                uint32_t h, l;
                split2(v0, v1, h, l);
                Chi[((size_t)r * N + c) >> 1] = h;
                Clo[((size_t)r * N + c) >> 1] = l;
                split2(v2, v3, h, l);
                Chi[((size_t)(r + 8) * N + c) >> 1] = h;
                Clo[((size_t)(r + 8) * N + c) >> 1] = l;
            } else {
                if (OUTMODE == 1) {
                    v0 += Rsd[(size_t)r * N + c];
                    v1 += Rsd[(size_t)r * N + c + 1];
                    v2 += Rsd[(size_t)(r + 8) * N + c];
                    v3 += Rsd[(size_t)(r + 8) * N + c + 1];
                }
                *(float2*)&C[(size_t)r * N + c]       = make_float2(v0, v1);
                *(float2*)&C[(size_t)(r + 8) * N + c] = make_float2(v2, v3);
            }
        }
    }
}

// ---------------- fused GEMM + residual + LayerNorm + split (N=256 full row) ----------------
// BM=32, BN=256: each CTA owns complete output rows -> row LN in the epilogue.
// MODE 0: C = A@B + bias, then LN -> Chi/Clo; Z gets pre-LN value.
// MODE 1: C = A@B + bias + Rsd, then LN -> Chi/Clo; Z gets pre-LN value.
#define FBM 32
#define FBST 264     // bf16 stride (528 B rows; 132 words ≡ 4 mod 32 banks, same as BST)
#define FBSTB 528
#define FLN_SMEM ((2*FBM*AST + 2*BK*FBST) * 2 * 2)   // 77824 bytes

template <int MODE>
__global__ __launch_bounds__(256) void gemm_fln(
    const __nv_bfloat16* __restrict__ Ah, const __nv_bfloat16* __restrict__ Al,
    const __nv_bfloat16* __restrict__ Bh, const __nv_bfloat16* __restrict__ Bl,
    const float* __restrict__ bias, const float* __restrict__ Rsd,
    const float* __restrict__ lng, const float* __restrict__ lnb,
    float* __restrict__ Z, uint32_t* __restrict__ Chi, uint32_t* __restrict__ Clo,
    int K)
{
    extern __shared__ char smem_raw[];
    __nv_bfloat16* sAh = (__nv_bfloat16*)smem_raw;
    __nv_bfloat16* sAl = sAh + 2 * FBM * AST;
    __nv_bfloat16* sBh = sAl + 2 * FBM * AST;
    __nv_bfloat16* sBl = sBh + 2 * BK * FBST;
    __shared__ float sS1[32][4], sS2[32][4];

    const int tid = threadIdx.x;
    const int warp = tid >> 5, lane = tid & 31;
    const int g = lane >> 2, tg = lane & 3;
    const int wy = warp >> 2, wx = warp & 3;
    const int row0 = blockIdx.x * FBM;

    float acc[8][4];
    #pragma unroll
    for (int a = 0; a < 8; a++)
        #pragma unroll
        for (int c = 0; c < 4; c++) acc[a][c] = 0.0f;

    auto issue = [&](int t, int b) {
        for (int s = tid; s < FBM * 4; s += 256) {
            int arow = s >> 2, aseg = s & 3;
            cp_async16(sAh + b * FBM * AST + arow * AST + aseg * 8,
                       Ah + (size_t)(row0 + arow) * K + t * BK + aseg * 8);
            cp_async16(sAl + b * FBM * AST + arow * AST + aseg * 8,
                       Al + (size_t)(row0 + arow) * K + t * BK + aseg * 8);
        }
        #pragma unroll
        for (int s = tid; s < 1024; s += 256) {
            int brow = s >> 5, bseg = s & 31;
            cp_async16(sBh + b * BK * FBST + brow * FBST + bseg * 8,
                       Bh + (size_t)(t * BK + brow) * 256 + bseg * 8);
            cp_async16(sBl + b * BK * FBST + brow * FBST + bseg * 8,
                       Bl + (size_t)(t * BK + brow) * 256 + bseg * 8);
        }
        cp_commit();
    };

    const int a_lane = (wy * 16 + (lane & 15)) * ASTB + (lane >> 4) * 16;
    const int b_lane = (lane & 15) * FBSTB + (lane >> 4) * 16 + wx * 128;

    auto compute = [&](int b) {
        uint32_t aHb = smem_u32(sAh + b * FBM * AST) + a_lane;
        uint32_t aLb = smem_u32(sAl + b * FBM * AST) + a_lane;
        uint32_t bHb = smem_u32(sBh + b * BK * FBST) + b_lane;
        uint32_t bLb = smem_u32(sBl + b * BK * FBST) + b_lane;

        #pragma unroll
        for (int ks = 0; ks < 2; ks++) {
            uint32_t ah[4], al[4], bh[4][4], bl[4][4];
            LDM4(ah[0], ah[1], ah[2], ah[3], aHb + ks * 32);
            LDM4(al[0], al[1], al[2], al[3], aLb + ks * 32);
            #pragma unroll
            for (int nc = 0; nc < 4; nc++) {
                LDM4T(bh[nc][0], bh[nc][1], bh[nc][2], bh[nc][3],
                      bHb + ks * 16 * FBSTB + nc * 32);
                LDM4T(bl[nc][0], bl[nc][1], bl[nc][2], bl[nc][3],
                      bLb + ks * 16 * FBSTB + nc * 32);
            }
            #pragma unroll
            for (int nf = 0; nf < 8; nf++) {
                const int p = nf >> 1, q = (nf & 1) * 2;
                MMA_BF16(acc[nf], al[0], al[1], al[2], al[3], bh[p][q], bh[p][q + 1]);
                MMA_BF16(acc[nf], ah[0], ah[1], ah[2], ah[3], bl[p][q], bl[p][q + 1]);
                MMA_BF16(acc[nf], ah[0], ah[1], ah[2], ah[3], bh[p][q], bh[p][q + 1]);
            }
        }
    };

    const int T = K / BK;
    issue(0, 0);
    for (int t = 0; t < T; t++) {
        const int buf = t & 1;
        if (t + 1 < T) {
            issue(t + 1, buf ^ 1);
            cp_wait<1>();
        } else {
            cp_wait<0>();
        }
        __syncthreads();
        compute(buf);
        __syncthreads();
    }

    // ---- epilogue: bias (+resid), write Z, row LN, split ----
    const int ra = row0 + wy * 16 + g;       // rows for acc[.][0],[1]
    const int rb = ra + 8;                   // rows for acc[.][2],[3]
    float vbuf[8][4];
    float s1a = 0.f, s2a = 0.f, s1b = 0.f, s2b = 0.f;
    #pragma unroll
    for (int nf = 0; nf < 8; nf++) {
        const int c = wx * 64 + nf * 8 + tg * 2;
        float v0 = acc[nf][0] + bias[c];
        float v1 = acc[nf][1] + bias[c + 1];
        float v2 = acc[nf][2] + bias[c];
        float v3 = acc[nf][3] + bias[c + 1];
        if (MODE == 1) {
            v0 += Rsd[(size_t)ra * 256 + c];
            v1 += Rsd[(size_t)ra * 256 + c + 1];
            v2 += Rsd[(size_t)rb * 256 + c];
            v3 += Rsd[(size_t)rb * 256 + c + 1];
        }
        *(float2*)&Z[(size_t)ra * 256 + c] = make_float2(v0, v1);
        *(float2*)&Z[(size_t)rb * 256 + c] = make_float2(v2, v3);
        vbuf[nf][0] = v0; vbuf[nf][1] = v1; vbuf[nf][2] = v2; vbuf[nf][3] = v3;
        s1a += v0 + v1;         s2a += v0 * v0 + v1 * v1;
        s1b += v2 + v3;         s2b += v2 * v2 + v3 * v3;
    }
    // reduce over tg lanes (same row, different columns)
    s1a += __shfl_xor_sync(~0u, s1a, 1);  s1a += __shfl_xor_sync(~0u, s1a, 2);
    s2a += __shfl_xor_sync(~0u, s2a, 1);  s2a += __shfl_xor_sync(~0u, s2a, 2);
    s1b += __shfl_xor_sync(~0u, s1b, 1);  s1b += __shfl_xor_sync(~0u, s1b, 2);
    s2b += __shfl_xor_sync(~0u, s2b, 1);  s2b += __shfl_xor_sync(~0u, s2b, 2);
    const int ria = wy * 16 + g, rib = ria + 8;
    if (tg == 0) {
        sS1[ria][wx] = s1a;  sS2[ria][wx] = s2a;
        sS1[rib][wx] = s1b;  sS2[rib][wx] = s2b;
    }
    __syncthreads();
    float suma = sS1[ria][0] + sS1[ria][1] + sS1[ria][2] + sS1[ria][3];
    float sqa  = sS2[ria][0] + sS2[ria][1] + sS2[ria][2] + sS2[ria][3];
    float sumb = sS1[rib][0] + sS1[rib][1] + sS1[rib][2] + sS1[rib][3];
    float sqb  = sS2[rib][0] + sS2[rib][1] + sS2[rib][2] + sS2[rib][3];
    const float inv = 1.0f / 256.0f;
    float mua = suma * inv, mub = sumb * inv;
    float rsa = rsqrtf(sqa * inv - mua * mua + 1e-5f);
    float rsb = rsqrtf(sqb * inv - mub * mub + 1e-5f);

    #pragma unroll
    for (int nf = 0; nf < 8; nf++) {
        const int c = wx * 64 + nf * 8 + tg * 2;
        float g0 = lng[c], g1 = lng[c + 1];
        float b0 = lnb[c], b1 = lnb[c + 1];
        float o0 = (vbuf[nf][0] - mua) * rsa * g0 + b0;
        float o1 = (vbuf[nf][1] - mua) * rsa * g1 + b1;
        float o2 = (vbuf[nf][2] - mub) * rsb * g0 + b0;
        float o3 = (vbuf[nf][3] - mub) * rsb * g1 + b1;
        uint32_t h, l;
        split2(o0, o1, h, l);
        Chi[((size_t)ra * 256 + c) >> 1] = h;
        Clo[((size_t)ra * 256 + c) >> 1] = l;
        split2(o2, o3, h, l);
        Chi[((size_t)rb * 256 + c) >> 1] = h;
        Clo[((size_t)rb * 256 + c) >> 1] = l;
    }
}

// ---------------- tensor-core flash attention (R7, unchanged) ----------------
#define QST 40
#define QSTB 80
#define ATTN_SMEM ((2*64*QST + 8*64*QST) * 2)

__global__ __launch_bounds__(128) void attn_mma(
    const uint32_t* __restrict__ qh, const uint32_t* __restrict__ ql,
    uint32_t* __restrict__ oh, uint32_t* __restrict__ ol)
{
    extern __shared__ char sm[];
    __nv_bfloat16* sQh = (__nv_bfloat16*)sm;
    __nv_bfloat16* sQl = sQh + 64 * QST;
    __nv_bfloat16* sKh = sQl + 64 * QST;
    __nv_bfloat16* sKl = sKh + 2 * 64 * QST;
    __nv_bfloat16* sVh = sKl + 2 * 64 * QST;
    __nv_bfloat16* sVl = sVh + 2 * 64 * QST;

    const int mh = blockIdx.x, qb = blockIdx.y;
    const int m = mh >> 3, h = mh & 7;
    const int q0 = qb * 64;
    const int tid = threadIdx.x, warp = tid >> 5, lane = tid & 31;
    const int g = lane >> 2, tg = lane & 3;
    const int tb = m * NTOK;
    const float scale = 0.17677669529663687f;

    const int i0 = tid * 2;
    const int lrow0 = i0 >> 2, lseg0 = i0 & 3;
    const int lrow1 = (i0 + 1) >> 2, lseg1 = (i0 + 1) & 3;

    {
        size_t s0 = (size_t)(tb + q0 + lrow0) * 384 + h * 16 + lseg0 * 4;
        size_t s1 = (size_t)(tb + q0 + lrow1) * 384 + h * 16 + lseg1 * 4;
        cp_async16(sQh + lrow0 * QST + lseg0 * 8, qh + s0);
        cp_async16(sQh + lrow1 * QST + lseg1 * 8, qh + s1);
        cp_async16(sQl + lrow0 * QST + lseg0 * 8, ql + s0);
        cp_async16(sQl + lrow1 * QST + lseg1 * 8, ql + s1);
        cp_commit();
    }
    auto issueKV = [&](int c, int b) {
        int k0 = c * 64;
        size_t s0 = (size_t)(tb + k0 + lrow0) * 384 + 128 + h * 16 + lseg0 * 4;
        size_t s1 = (size_t)(tb + k0 + lrow1) * 384 + 128 + h * 16 + lseg1 * 4;
        __nv_bfloat16* kh = sKh + b * 64 * QST;
        __nv_bfloat16* kl = sKl + b * 64 * QST;
        __nv_bfloat16* vh = sVh + b * 64 * QST;
        __nv_bfloat16* vl = sVl + b * 64 * QST;
        cp_async16(kh + lrow0 * QST + lseg0 * 8, qh + s0);
        cp_async16(kh + lrow1 * QST + lseg1 * 8, qh + s1);
        cp_async16(kl + lrow0 * QST + lseg0 * 8, ql + s0);
        cp_async16(kl + lrow1 * QST + lseg1 * 8, ql + s1);
        cp_async16(vh + lrow0 * QST + lseg0 * 8, qh + s0 + 128);
        cp_async16(vh + lrow1 * QST + lseg1 * 8, qh + s1 + 128);
        cp_async16(vl + lrow0 * QST + lseg0 * 8, ql + s0 + 128);
        cp_async16(vl + lrow1 * QST + lseg1 * 8, ql + s1 + 128);
        cp_commit();
    };

    issueKV(0, 0);
    cp_wait<1>();
    __syncthreads();

    uint32_t qfh[2][4], qfl[2][4];
    {
        uint32_t bh_ = smem_u32(sQh) + (warp * 16 + (lane & 15)) * QSTB + (lane >> 4) * 16;
        uint32_t bl_ = smem_u32(sQl) + (warp * 16 + (lane & 15)) * QSTB + (lane >> 4) * 16;
        LDM4(qfh[0][0], qfh[0][1], qfh[0][2], qfh[0][3], bh_);
        LDM4(qfh[1][0], qfh[1][1], qfh[1][2], qfh[1][3], bh_ + 32);
        LDM4(qfl[0][0], qfl[0][1], qfl[0][2], qfl[0][3], bl_);
        LDM4(qfl[1][0], qfl[1][1], qfl[1][2], qfl[1][3], bl_ + 32);
    }

    float mx0 = -1e30f, mx1 = -1e30f, sum0 = 0.f, sum1 = 0.f;
    float oacc[4][4];
    #pragma unroll
    for (int a = 0; a < 4; a++)
        #pragma unroll
        for (int b = 0; b < 4; b++) oacc[a][b] = 0.f;

    const uint32_t kbyte = ((lane & 7) + ((lane >> 4) & 1) * 8) * QSTB +
                           ((lane >> 3) & 1) * 16;
    const uint32_t vbyte = (lane & 15) * QSTB + (lane >> 4) * 16;

    for (int c = 0; c < 8; c++) {
        const int b = c & 1;
        if (c + 1 < 8) { issueKV(c + 1, b ^ 1); cp_wait<1>(); }
        else           { cp_wait<0>(); }
        __syncthreads();

        uint32_t khb = smem_u32(sKh + b * 64 * QST) + kbyte;
        uint32_t klb = smem_u32(sKl + b * 64 * QST) + kbyte;

        float sacc[8][4];
        #pragma unroll
        for (int a = 0; a < 8; a++)
            #pragma unroll
            for (int j = 0; j < 4; j++) sacc[a][j] = 0.f;

        #pragma unroll
        for (int nk = 0; nk < 4; nk++) {
            uint32_t kh0[4], kh1[4], kl0[4], kl1[4];
            LDM4(kh0[0], kh0[1], kh0[2], kh0[3], khb + nk * 16 * QSTB);
            LDM4(kh1[0], kh1[1], kh1[2], kh1[3], khb + nk * 16 * QSTB + 32);
            LDM4(kl0[0], kl0[1], kl0[2], kl0[3], klb + nk * 16 * QSTB);
            LDM4(kl1[0], kl1[1], kl1[2], kl1[3], klb + nk * 16 * QSTB + 32);
            MMA_BF16(sacc[nk*2], qfl[0][0], qfl[0][1], qfl[0][2], qfl[0][3], kh0[0], kh0[1]);
            MMA_BF16(sacc[nk*2], qfl[1][0], qfl[1][1], qfl[1][2], qfl[1][3], kh1[0], kh1[1]);
            MMA_BF16(sacc[nk*2], qfh[0][0], qfh[0][1], qfh[0][2], qfh[0][3], kl0[0], kl0[1]);
            MMA_BF16(sacc[nk*2], qfh[1][0], qfh[1][1], qfh[1][2], qfh[1][3], kl1[0], kl1[1]);
            MMA_BF16(sacc[nk*2], qfh[0][0], qfh[0][1], qfh[0][2], qfh[0][3], kh0[0], kh0[1]);
            MMA_BF16(sacc[nk*2], qfh[1][0], qfh[1][1], qfh[1][2], qfh[1][3], kh1[0], kh1[1]);
            MMA_BF16(sacc[nk*2+1], qfl[0][0], qfl[0][1], qfl[0][2], qfl[0][3], kh0[2], kh0[3]);
            MMA_BF16(sacc[nk*2+1], qfl[1][0], qfl[1][1], qfl[1][2], qfl[1][3], kh1[2], kh1[3]);
            MMA_BF16(sacc[nk*2+1], qfh[0][0], qfh[0][1], qfh[0][2], qfh[0][3], kl0[2], kl0[3]);
            MMA_BF16(sacc[nk*2+1], qfh[1][0], qfh[1][1], qfh[1][2], qfh[1][3], kl1[2], kl1[3]);
            MMA_BF16(sacc[nk*2+1], qfh[0][0], qfh[0][1], qfh[0][2], qfh[0][3], kh0[2], kh0[3]);
            MMA_BF16(sacc[nk*2+1], qfh[1][0], qfh[1][1], qfh[1][2], qfh[1][3], kh1[2], kh1[3]);
        }

        float cm0 = -1e30f, cm1 = -1e30f;
        #pragma unroll
        for (int a = 0; a < 8; a++) {
            #pragma unroll
            for (int j = 0; j < 4; j++) sacc[a][j] *= scale;
            cm0 = fmaxf(cm0, fmaxf(sacc[a][0], sacc[a][1]));
            cm1 = fmaxf(cm1, fmaxf(sacc[a][2], sacc[a][3]));
        }
        cm0 = fmaxf(cm0, __shfl_xor_sync(~0u, cm0, 1));
        cm0 = fmaxf(cm0, __shfl_xor_sync(~0u, cm0, 2));
        cm1 = fmaxf(cm1, __shfl_xor_sync(~0u, cm1, 1));
        cm1 = fmaxf(cm1, __shfl_xor_sync(~0u, cm1, 2));
        float nm0 = fmaxf(mx0, cm0), nm1 = fmaxf(mx1, cm1);
        float c0 = __expf(mx0 - nm0), c1 = __expf(mx1 - nm1);
        sum0 *= c0; sum1 *= c1;
        #pragma unroll
        for (int a = 0; a < 4; a++) {
            oacc[a][0] *= c0; oacc[a][1] *= c0;
            oacc[a][2] *= c1; oacc[a][3] *= c1;
        }
        #pragma unroll
        for (int a = 0; a < 8; a++) {
            sacc[a][0] = __expf(sacc[a][0] - nm0);
            sacc[a][1] = __expf(sacc[a][1] - nm0);
            sacc[a][2] = __expf(sacc[a][2] - nm1);
            sacc[a][3] = __expf(sacc[a][3] - nm1);
            sum0 += sacc[a][0] + sacc[a][1];
            sum1 += sacc[a][2] + sacc[a][3];
        }
        mx0 = nm0; mx1 = nm1;

        uint32_t pah[4][4], pal[4][4];
        #pragma unroll
        for (int kf = 0; kf < 4; kf++) {
            split2(sacc[kf*2][0],   sacc[kf*2][1],   pah[kf][0], pal[kf][0]);
            split2(sacc[kf*2][2],   sacc[kf*2][3],   pah[kf][1], pal[kf][1]);
            split2(sacc[kf*2+1][0], sacc[kf*2+1][1], pah[kf][2], pal[kf][2]);
            split2(sacc[kf*2+1][2], sacc[kf*2+1][3], pah[kf][3], pal[kf][3]);
        }

        uint32_t vhb = smem_u32(sVh + b * 64 * QST) + vbyte;
        uint32_t vlb = smem_u32(sVl + b * 64 * QST) + vbyte;
        #pragma unroll
        for (int nc = 0; nc < 2; nc++) {
            #pragma unroll
            for (int kf = 0; kf < 4; kf++) {
                uint32_t vh_[4], vl_[4];
                LDM4T(vh_[0], vh_[1], vh_[2], vh_[3], vhb + kf * 16 * QSTB + nc * 32);
                LDM4T(vl_[0], vl_[1], vl_[2], vl_[3], vlb + kf * 16 * QSTB + nc * 32);
                MMA_BF16(oacc[nc*2], pal[kf][0], pal[kf][1], pal[kf][2], pal[kf][3], vh_[0], vh_[1]);
                MMA_BF16(oacc[nc*2], pah[kf][0], pah[kf][1], pah[kf][2], pah[kf][3], vl_[0], vl_[1]);
                MMA_BF16(oacc[nc*2], pah[kf][0], pah[kf][1], pah[kf][2], pah[kf][3], vh_[0], vh_[1]);
                MMA_BF16(oacc[nc*2+1], pal[kf][0], pal[kf][1], pal[kf][2], pal[kf][3], vh_[2], vh_[3]);
                MMA_BF16(oacc[nc*2+1], pah[kf][0], pah[kf][1], pah[kf][2], pah[kf][3], vl_[2], vl_[3]);
                MMA_BF16(oacc[nc*2+1], pah[kf][0], pah[kf][1], pah[kf][2], pah[kf][3], vh_[2], vh_[3]);
            }
        }
        __syncthreads();
    }

    if (q0 >= NCC) {
        #pragma unroll
        for (int half = 0; half < 2; half++) {
            int row = q0 + warp * 16 + g + half * 8;
            size_t pb = (size_t)(tb + row) * 384;
            float dot = 0.f;
            #pragma unroll
            for (int w = 0; w < 4; w++) {
                uint32_t qhv = qh[pb + h * 16 + tg * 4 + w];
                uint32_t qlv = ql[pb + h * 16 + tg * 4 + w];
                uint32_t khv = qh[pb + 128 + h * 16 + tg * 4 + w];
                uint32_t klv = ql[pb + 128 + h * 16 + tg * 4 + w];
                float qa = bflo(qhv) + bflo(qlv), qb_ = bfhi(qhv) + bfhi(qlv);
                float ka = bflo(khv) + bflo(klv), kb = bfhi(khv) + bfhi(klv);
                dot += qa * ka + qb_ * kb;
            }
            dot += __shfl_xor_sync(~0u, dot, 1);
            dot += __shfl_xor_sync(~0u, dot, 2);
            float s = dot * scale;
            float mxv = half ? mx1 : mx0;
            float nm = fmaxf(mxv, s);
            float corr = __expf(mxv - nm);
            float p = __expf(s - nm);
            if (half) { sum1 = sum1 * corr + (tg == 0 ? p : 0.f); mx1 = nm; }
            else      { sum0 = sum0 * corr + (tg == 0 ? p : 0.f); mx0 = nm; }
            #pragma unroll
            for (int nf = 0; nf < 4; nf++) {
                uint32_t vhv = qh[pb + 256 + h * 16 + nf * 4 + tg];
                uint32_t vlv = ql[pb + 256 + h * 16 + nf * 4 + tg];
                float v0 = bflo(vhv) + bflo(vlv);
                float v1 = bfhi(vhv) + bfhi(vlv);
                oacc[nf][half*2]   = oacc[nf][half*2]   * corr + p * v0;
                oacc[nf][half*2+1] = oacc[nf][half*2+1] * corr + p * v1;
            }
        }
    }

    sum0 += __shfl_xor_sync(~0u, sum0, 1);
    sum0 += __shfl_xor_sync(~0u, sum0, 2);
    sum1 += __shfl_xor_sync(~0u, sum1, 1);
    sum1 += __shfl_xor_sync(~0u, sum1, 2);
    float inv0 = 1.f / sum0, inv1 = 1.f / sum1;

    int row = q0 + warp * 16 + g;
    size_t ob0 = ((size_t)(tb + row) * 256 + h * 32) >> 1;
    size_t ob1 = ((size_t)(tb + row + 8) * 256 + h * 32) >> 1;
    #pragma unroll
    for (int nf = 0; nf < 4; nf++) {
        uint32_t hh_, ll_;
        split2(oacc[nf][0] * inv0, oacc[nf][1] * inv0, hh_, ll_);
        oh[ob0 + nf * 4 + tg] = hh_;
        ol[ob0 + nf * 4 + tg] = ll_;
        split2(oacc[nf][2] * inv1, oacc[nf][3] * inv1, hh_, ll_);
        oh[ob1 + nf * 4 + tg] = hh_;
        ol[ob1 + nf * 4 + tg] = ll_;
    }
}

// ---------------- encoder layer-1 ----------------
__global__ __launch_bounds__(128) void encode_hidden(
    const float* __restrict__ xc, const float* __restrict__ yc,
    const float* __restrict__ xt,
    const float* __restrict__ W1, const float* __restrict__ b1,
    uint32_t* __restrict__ hh, uint32_t* __restrict__ hl)
{
    int tok = blockIdx.x;
    int m = tok >> 10, t = tok & 1023;
    int tid = threadIdx.x;
    int d = tid * 2;

    __shared__ float s_in[16];
    if (tid < 10) {
        float v;
        if (tid < 8) {
            v = (t < NCC) ? xc[(m * NCC + t) * 8 + tid]
                          : xt[(m * NCC + (t - NCC)) * 8 + tid];
        } else if (tid == 8) {
            v = (t < NCC) ? yc[m * NCC + t] : 0.0f;
        } else {
            v = (t < NCC) ? 0.0f : 1.0f;
        }
        s_in[tid] = v;
    }
    __syncthreads();

    float a0 = b1[d], a1 = b1[d + 1];
    #pragma unroll
    for (int k = 0; k < 10; k++) {
        a0 += s_in[k] * W1[k * DMOD + d];
        a1 += s_in[k] * W1[k * DMOD + d + 1];
    }
    uint32_t h, l;
    split2(fmaxf(a0, 0.0f), fmaxf(a1, 0.0f), h, l);
    hh[tok * 128 + tid] = h;
    hl[tok * 128 + tid] = l;
}

// ---------------- layernorm (warp/token), split bf16 output — for ln1 after FF2 ----------------
__global__ __launch_bounds__(256) void ln_kernel(
    const float* __restrict__ x, const float* __restrict__ g,
    const float* __restrict__ b,
    uint32_t* __restrict__ yh, uint32_t* __restrict__ yl)
{
    int tok  = (blockIdx.x * 256 + threadIdx.x) >> 5;
    int lane = threadIdx.x & 31;

    const float4* xp = (const float4*)(x + (size_t)tok * DMOD);
    float4 v0 = xp[lane * 2], v1 = xp[lane * 2 + 1];

    float s = v0.x + v0.y + v0.z + v0.w + v1.x + v1.y + v1.z + v1.w;
    #pragma unroll
    for (int o = 16; o > 0; o >>= 1) s += __shfl_xor_sync(0xffffffffu, s, o);
    float mu = s * (1.0f / DMOD);

    float d0 = v0.x - mu, d1 = v0.y - mu, d2 = v0.z - mu, d3 = v0.w - mu;
    float d4 = v1.x - mu, d5 = v1.y - mu, d6 = v1.z - mu, d7 = v1.w - mu;
    float q = d0*d0 + d1*d1 + d2*d2 + d3*d3 + d4*d4 + d5*d5 + d6*d6 + d7*d7;
    #pragma unroll
    for (int o = 16; o > 0; o >>= 1) q += __shfl_xor_sync(0xffffffffu, q, o);
    float rstd = rsqrtf(q * (1.0f / DMOD) + 1e-5f);

    const float4* gp = (const float4*)g;
    const float4* bp = (const float4*)b;
    float4 g0 = gp[lane * 2], g1 = gp[lane * 2 + 1];
    float4 b0 = bp[lane * 2], b1 = bp[lane * 2 + 1];

    float o0 = d0 * rstd * g0.x + b0.x, o1 = d1 * rstd * g0.y + b0.y;
    float o2 = d2 * rstd * g0.z + b0.z, o3 = d3 * rstd * g0.w + b0.w;
    float o4 = d4 * rstd * g1.x + b1.x, o5 = d5 * rstd * g1.y + b1.y;
    float o6 = d6 * rstd * g1.z + b1.z, o7 = d7 * rstd * g1.w + b1.w;

    uint32_t h, l;
    int base = tok * 128 + lane * 4;
    split2(o0, o1, h, l);  yh[base + 0] = h;  yl[base + 0] = l;
    split2(o2, o3, h, l);  yh[base + 1] = h;  yl[base + 1] = l;
    split2(o4, o5, h, l);  yh[base + 2] = h;  yl[base + 2] = l;
    split2(o6, o7, h, l);  yh[base + 3] = h;  yl[base + 3] = l;
}

// ---------------- launch ----------------
#define BF16P(sym) ((const __nv_bfloat16*)sym)

extern "C" void kernel_launch(void* const* d_in, const int* in_sizes, int n_in,
                              void* d_out, int out_size)
{
    const float* xc     = (const float*)d_in[0];
    const float* yc     = (const float*)d_in[1];
    const float* xt     = (const float*)d_in[2];
    const float* enc_W1 = (const float*)d_in[3];
    const float* enc_b1 = (const float*)d_in[4];
    const float* enc_W2 = (const float*)d_in[5];
    const float* enc_b2 = (const float*)d_in[6];
    const float* Wqkv   = (const float*)d_in[7];
    const float* bqkv   = (const float*)d_in[8];
    const float* Wo     = (const float*)d_in[9];
    const float* bo     = (const float*)d_in[10];
    const float* ln1_g  = (const float*)d_in[11];
    const float* ln1_b  = (const float*)d_in[12];
    const float* ln2_g  = (const float*)d_in[13];
    const float* ln2_b  = (const float*)d_in[14];
    const float* Wff1   = (const float*)d_in[15];
    const float* bff1   = (const float*)d_in[16];
    const float* Wff2   = (const float*)d_in[17];
    const float* bff2   = (const float*)d_in[18];
    float* out          = (float*)d_out;

    float* z;
    uint32_t *hh, *hl, *qkh, *qkl, *ah, *al, *fh, *fl;
    uint32_t *wqh, *wql, *woh, *wol, *w1h, *w1l, *w2h, *w2l, *ewh, *ewl;
    cudaGetSymbolAddress((void**)&z,   g_z);
    cudaGetSymbolAddress((void**)&hh,  g_h_h);   cudaGetSymbolAddress((void**)&hl,  g_h_l);
    cudaGetSymbolAddress((void**)&qkh, g_qkv_h); cudaGetSymbolAddress((void**)&qkl, g_qkv_l);
    cudaGetSymbolAddress((void**)&ah,  g_att_h); cudaGetSymbolAddress((void**)&al,  g_att_l);
    cudaGetSymbolAddress((void**)&fh,  g_ff_h);  cudaGetSymbolAddress((void**)&fl,  g_ff_l);
    cudaGetSymbolAddress((void**)&wqh, g_wqkv_h); cudaGetSymbolAddress((void**)&wql, g_wqkv_l);
    cudaGetSymbolAddress((void**)&woh, g_wo_h);   cudaGetSymbolAddress((void**)&wol, g_wo_l);
    cudaGetSymbolAddress((void**)&w1h, g_wff1_h); cudaGetSymbolAddress((void**)&w1l, g_wff1_l);
    cudaGetSymbolAddress((void**)&w2h, g_wff2_h); cudaGetSymbolAddress((void**)&w2l, g_wff2_l);
    cudaGetSymbolAddress((void**)&ewh, g_ew2_h);  cudaGetSymbolAddress((void**)&ewl, g_ew2_l);

    const int SM128 = GEMM_SMEM(128);
    const int SM64  = GEMM_SMEM(64);
    cudaFuncSetAttribute(gemm_bf3<1, 64>,  cudaFuncAttributeMaxDynamicSharedMemorySize, SM64);
    cudaFuncSetAttribute(gemm_bf3<2, 128>, cudaFuncAttributeMaxDynamicSharedMemorySize, SM128);
    cudaFuncSetAttribute(gemm_bf3<3, 128>, cudaFuncAttributeMaxDynamicSharedMemorySize, SM128);
    cudaFuncSetAttribute(gemm_fln<0>, cudaFuncAttributeMaxDynamicSharedMemorySize, FLN_SMEM);
    cudaFuncSetAttribute(gemm_fln<1>, cudaFuncAttributeMaxDynamicSharedMemorySize, FLN_SMEM);
    cudaFuncSetAttribute(attn_mma, cudaFuncAttributeMaxDynamicSharedMemorySize, ATTN_SMEM);

    // merged weight split (one launch)
    split_all<<<(P_TOT + 255) / 256, 256>>>(enc_W2, Wqkv, Wo, Wff1, Wff2);

    // encoder: hidden -> fused GEMM + LN1(layer 0) (in-place hh/hl is safe: full-N tiles)
    encode_hidden<<<TOK, 128>>>(xc, yc, xt, enc_W1, enc_b1, hh, hl);
    gemm_fln<0><<<TOK / FBM, 256, FLN_SMEM>>>(
        BF16P(hh), BF16P(hl), BF16P(ewh), BF16P(ewl),
        enc_b2, nullptr, ln1_g, ln1_b, z, hh, hl, DMOD);

    for (int l = 0; l < NLAY; l++) {
        const uint32_t* wq_h = wqh + (size_t)l * DMOD * 3 * DMOD / 2;
        const uint32_t* wq_l = wql + (size_t)l * DMOD * 3 * DMOD / 2;
        const uint32_t* wo_h = woh + (size_t)l * DMOD * DMOD / 2;
        const uint32_t* wo_l = wol + (size_t)l * DMOD * DMOD / 2;
        const uint32_t* f1_h = w1h + (size_t)l * DMOD * FFD / 2;
        const uint32_t* f1_l = w1l + (size_t)l * DMOD * FFD / 2;
        const uint32_t* f2_h = w2h + (size_t)l * FFD * DMOD / 2;
        const uint32_t* f2_l = w2l + (size_t)l * FFD * DMOD / 2;

        // QKV from hh/hl (= LN1 output)
        gemm_bf3<3, 128><<<dim3(3 * DMOD / BN, TOK / 128), 256, SM128>>>(
            BF16P(hh), BF16P(hl), BF16P(wq_h), BF16P(wq_l),
            bqkv + l * 3 * DMOD, nullptr, nullptr, qkh, qkl, DMOD, 3 * DMOD);
        attn_mma<<<dim3(MB * NH, NTOK / 64), 128, ATTN_SMEM>>>(qkh, qkl, ah, al);
        // Wo + residual + LN2 fused: z updated, hh/hl = LN2 output
        gemm_fln<1><<<TOK / FBM, 256, FLN_SMEM>>>(
            BF16P(ah), BF16P(al), BF16P(wo_h), BF16P(wo_l),
            bo + l * DMOD, z, ln2_g + l * DMOD, ln2_b + l * DMOD,
            z, hh, hl, DMOD);
        // FF1 from hh/hl (= LN2 output)
        gemm_bf3<2, 128><<<dim3(FFD / BN, TOK / 128), 256, SM128>>>(
            BF16P(hh), BF16P(hl), BF16P(f1_h), BF16P(f1_l),
            bff1 + l * FFD, nullptr, nullptr, fh, fl, DMOD, FFD);
        // FF2 + residual
        float* dst = (l == NLAY - 1) ? out : z;
        gemm_bf3<1, 64><<<dim3(DMOD / BN, TOK / 64), 256, SM64>>>(
            BF16P(fh), BF16P(fl), BF16P(f2_h), BF16P(f2_l),
            bff2 + l * DMOD, z, dst, nullptr, nullptr, FFD, DMOD);
        // LN1 for next layer (separate — FF2 weight too large for full-N fusion)
        if (l + 1 < NLAY) {
            ln_kernel<<<TOK / 8, 256>>>(z, ln1_g + (l + 1) * DMOD,
                                        ln1_b + (l + 1) * DMOD, hh, hl);
        }
    }
}